// round 12
// baseline (speedup 1.0000x reference)
#include <cuda_runtime.h>
#include <cuda_fp16.h>
#include <stdint.h>
#include <math.h>

// ---------------------------------------------------------------------------
// Problem constants
// ---------------------------------------------------------------------------
#define N_EMBD 2048
#define NH     16
#define HD     128
#define TT     2048
#define BB     2
#define MROWS  (BB * TT)
#define QKV_N  (3 * N_EMBD)

// ---------------------------------------------------------------------------
// Scratch
// ---------------------------------------------------------------------------
__device__ float g_cos[TT * (HD / 2)];
__device__ float g_sin[TT * (HD / 2)];
__device__ __half g_Ah[(size_t)MROWS * N_EMBD];
__device__ __half g_Al[(size_t)MROWS * N_EMBD];
__device__ __half g_Wa[(size_t)QKV_N * N_EMBD];
__device__ __half g_Wp[(size_t)N_EMBD * N_EMBD];
__device__ __half g_Qh[(size_t)MROWS * N_EMBD];
__device__ __half g_Ql[(size_t)MROWS * N_EMBD];
__device__ __half g_K [(size_t)MROWS * N_EMBD];
__device__ __half g_Vh[(size_t)MROWS * N_EMBD];
__device__ __half g_Vt[(size_t)MROWS * N_EMBD];

// ---------------------------------------------------------------------------
// Helpers
// ---------------------------------------------------------------------------
__device__ __forceinline__ uint32_t smem_u32(const void* p) {
    uint32_t a;
    asm("{ .reg .u64 t; cvta.to.shared.u64 t, %1; cvt.u32.u64 %0, t; }"
        : "=r"(a) : "l"(p));
    return a;
}

__device__ __forceinline__ void ldsm_x4(uint32_t* r, uint32_t addr) {
    asm volatile("ldmatrix.sync.aligned.m8n8.x4.shared.b16 {%0,%1,%2,%3}, [%4];"
                 : "=r"(r[0]), "=r"(r[1]), "=r"(r[2]), "=r"(r[3]) : "r"(addr));
}

// fp32-accumulator fp16 MMA
__device__ __forceinline__ void mma16816(float* c, const uint32_t* a,
                                         const uint32_t* b) {
    asm volatile(
        "mma.sync.aligned.m16n8k16.row.col.f32.f16.f16.f32 "
        "{%0,%1,%2,%3}, {%4,%5,%6,%7}, {%8,%9}, {%0,%1,%2,%3};"
        : "+f"(c[0]), "+f"(c[1]), "+f"(c[2]), "+f"(c[3])
        : "r"(a[0]), "r"(a[1]), "r"(a[2]), "r"(a[3]), "r"(b[0]), "r"(b[1]));
}

// fp16-accumulator fp16 MMA (possible 2x rate)
__device__ __forceinline__ void mma16816h(uint32_t* c, const uint32_t* a,
                                          const uint32_t* b) {
    asm volatile(
        "mma.sync.aligned.m16n8k16.row.col.f16.f16.f16.f16 "
        "{%0,%1}, {%2,%3,%4,%5}, {%6,%7}, {%0,%1};"
        : "+r"(c[0]), "+r"(c[1])
        : "r"(a[0]), "r"(a[1]), "r"(a[2]), "r"(a[3]), "r"(b[0]), "r"(b[1]));
}

// merge packed fp16 D-fragment into fp32 accumulator fragment
__device__ __forceinline__ void merge_lo(float* c, const uint32_t* d) {
    float2 f0 = __half22float2(*(const __half2*)&d[0]);
    float2 f1 = __half22float2(*(const __half2*)&d[1]);
    c[0] += f0.x; c[1] += f0.y; c[2] += f1.x; c[3] += f1.y;
}

#define CP_ASYNC16(dst, src) \
    asm volatile("cp.async.cg.shared.global [%0], [%1], 16;" \
                 :: "r"(dst), "l"(src) : "memory")
#define CP_COMMIT() asm volatile("cp.async.commit_group;" ::: "memory")
#define CP_WAIT1()  asm volatile("cp.async.wait_group 1;" ::: "memory")

__device__ __forceinline__ void pack_hl(float x, float y, uint32_t& h, uint32_t& l) {
    __half2 hh = __floats2half2_rn(x, y);
    float rx = x - __half2float(__low2half(hh));
    float ry = y - __half2float(__high2half(hh));
    __half2 ll = __floats2half2_rn(rx, ry);
    h = *(uint32_t*)&hh;
    l = *(uint32_t*)&ll;
}

// ---------------------------------------------------------------------------
// Convert kernels
// ---------------------------------------------------------------------------
__global__ void conv_rm_kernel(const float* __restrict__ in,
                               __half* __restrict__ oh,
                               __half* __restrict__ ol, int n4) {
    int idx = blockIdx.x * blockDim.x + threadIdx.x;
    if (idx >= n4) return;
    float4 v = ((const float4*)in)[idx];
    __half2 h01 = __floats2half2_rn(v.x, v.y);
    __half2 h23 = __floats2half2_rn(v.z, v.w);
    __half2 l01 = __floats2half2_rn(v.x - __half2float(__low2half(h01)),
                                    v.y - __half2float(__high2half(h01)));
    __half2 l23 = __floats2half2_rn(v.z - __half2float(__low2half(h23)),
                                    v.w - __half2float(__high2half(h23)));
    ((__half2*)oh)[idx * 2]     = h01;
    ((__half2*)oh)[idx * 2 + 1] = h23;
    ((__half2*)ol)[idx * 2]     = l01;
    ((__half2*)ol)[idx * 2 + 1] = l23;
}

__global__ void conv_tr_kernel(const float* __restrict__ B,
                               __half* __restrict__ bt, int K, int N) {
    __shared__ float tile[32][33];
    int n0 = blockIdx.x * 32, k0 = blockIdx.y * 32;
    int tx = threadIdx.x, ty = threadIdx.y;
#pragma unroll
    for (int i = 0; i < 4; i++)
        tile[ty + i * 8][tx] = B[(size_t)(k0 + ty + i * 8) * N + n0 + tx];
    __syncthreads();
#pragma unroll
    for (int i = 0; i < 4; i++) {
        int n = ty + i * 8;
        bt[(size_t)(n0 + n) * K + k0 + tx] = __float2half_rn(tile[tx][n]);
    }
}

__global__ void conv_vth_kernel(const __half* __restrict__ vh,
                                __half* __restrict__ vt) {
    __shared__ __half tile[32][34];
    int bh = blockIdx.z;
    int b = bh >> 4, h = bh & 15;
    int t0 = blockIdx.x * 32, d0 = blockIdx.y * 32;
    int tx = threadIdx.x, ty = threadIdx.y;
#pragma unroll
    for (int i = 0; i < 4; i++)
        tile[ty + i * 8][tx] =
            vh[(size_t)(b * TT + t0 + ty + i * 8) * N_EMBD + h * HD + d0 + tx];
    __syncthreads();
#pragma unroll
    for (int i = 0; i < 4; i++) {
        int d = ty + i * 8;
        vt[(size_t)(bh * HD + d0 + d) * TT + t0 + tx] = tile[tx][d];
    }
}

__global__ void rope_table_kernel() {
    int idx = blockIdx.x * blockDim.x + threadIdx.x;
    if (idx >= TT * 64) return;
    int t = idx >> 6;
    int i = idx & 63;
    double theta = pow(10000.0, -(double)i / 64.0);
    double ang = (double)t * theta;
    g_cos[idx] = (float)cos(ang);
    g_sin[idx] = (float)sin(ang);
}

// ---------------------------------------------------------------------------
// GEMM config
// ---------------------------------------------------------------------------
#define BM 128
#define BK 32
#define PADB 80
#define A_BYTES (128 * PADB)           // 10240 per A matrix (hi or lo)

// QKV kernel: BN=192 (wave-efficient for N=6144)
#define BN6 192
#define B6_BYTES (192 * PADB)                   // 15360
#define STG6 (2 * A_BYTES + B6_BYTES)           // 35840
#define QKV_SMEM (2 * STG6)                     // 71680

// Proj kernel: BN=128
#define BN4 128
#define B4_BYTES (128 * PADB)                   // 10240
#define STG4 (2 * A_BYTES + B4_BYTES)           // 30720
#define PROJ_SMEM (2 * STG4)                    // 61440

// ---------------------------------------------------------------------------
// QKV GEMM (BN=192): hi-term fp32-acc, lo-term fp16-acc; fused RoPE epilogue.
// Section boundary (2048) may fall inside a tile -> per-fragment sec.
// ---------------------------------------------------------------------------
__global__ __launch_bounds__(256, 1) void gemm_qkv_kernel(
    const __half* __restrict__ Ah, const __half* __restrict__ Al,
    const __half* __restrict__ B,
    __half* __restrict__ Qh, __half* __restrict__ Ql,
    __half* __restrict__ Kb, __half* __restrict__ Vh)
{
    const int K = N_EMBD;
    extern __shared__ char smc[];
    const uint32_t sbase = smem_u32(smc);
    const int tid = threadIdx.x;
    const int lane = tid & 31;
    const int wid = tid >> 5;
    const int wm = wid & 1;            // 2 warps in M (64 rows)
    const int wn = wid >> 1;           // 4 warps in N (48 cols)
    const int mBase = blockIdx.y * BM;
    const int nBase = blockIdx.x * BN6;
    const int nch = K / BK;

    const int ldRow = tid >> 2;
    const int ldCh  = tid & 3;

    float acc[4][6][4];
    uint32_t lacc[4][6][2];
#pragma unroll
    for (int i = 0; i < 4; i++)
#pragma unroll
        for (int j = 0; j < 6; j++) {
#pragma unroll
            for (int r = 0; r < 4; r++) acc[i][j][r] = 0.0f;
            lacc[i][j][0] = 0u; lacc[i][j][1] = 0u;
        }

    auto issue_stage = [&](int c, int buf) {
        const uint32_t st = sbase + buf * STG6;
        const int kOff = c * BK;
#pragma unroll
        for (int i = 0; i < 2; i++) {
            const int row = i * 64 + ldRow;
            const uint32_t so = row * PADB + ldCh * 16;
            CP_ASYNC16(st + so,
                       Ah + (size_t)(mBase + row) * K + kOff + ldCh * 8);
            CP_ASYNC16(st + A_BYTES + so,
                       Al + (size_t)(mBase + row) * K + kOff + ldCh * 8);
        }
#pragma unroll
        for (int i = 0; i < 3; i++) {
            const int row = i * 64 + ldRow;
            const uint32_t so = row * PADB + ldCh * 16;
            CP_ASYNC16(st + 2 * A_BYTES + so,
                       B + (size_t)(nBase + row) * K + kOff + ldCh * 8);
        }
    };

    issue_stage(0, 0);
    CP_COMMIT();

    const int arow = (lane & 7) + ((lane >> 3) & 1) * 8;
    const int akc8 = (lane >> 4) * 8;
    const int brow = (lane & 7) + ((lane >> 4) & 1) * 8;
    const int bkc8 = ((lane >> 3) & 1) * 8;

    for (int c = 0; c < nch; c++) {
        const int buf = c & 1;
        if (c + 1 < nch) issue_stage(c + 1, (c + 1) & 1);
        CP_COMMIT();
        CP_WAIT1();
        __syncthreads();

        const uint32_t st = sbase + buf * STG6;
        const uint32_t ahB = st;
        const uint32_t alB = st + A_BYTES;
        const uint32_t bB  = st + 2 * A_BYTES;

#pragma unroll
        for (int s = 0; s < 2; s++) {
            const int kofs = s * 16;
            uint32_t ah[4][4], al[4][4];
#pragma unroll
            for (int fm = 0; fm < 4; fm++) {
                const uint32_t off =
                    (uint32_t)((wm * 64 + fm * 16 + arow) * PADB +
                               (kofs + akc8) * 2);
                ldsm_x4(ah[fm], ahB + off);
                ldsm_x4(al[fm], alB + off);
            }
#pragma unroll
            for (int bi = 0; bi < 3; bi++) {
                uint32_t bf[4];
                const uint32_t off =
                    (uint32_t)((wn * 48 + bi * 16 + brow) * PADB +
                               (kofs + bkc8) * 2);
                ldsm_x4(bf, bB + off);
#pragma unroll
                for (int fm = 0; fm < 4; fm++) {
                    mma16816(acc[fm][2 * bi],     ah[fm], bf);
                    mma16816(acc[fm][2 * bi + 1], ah[fm], bf + 2);
                }
#pragma unroll
                for (int fm = 0; fm < 4; fm++) {
                    mma16816h(lacc[fm][2 * bi],     al[fm], bf);
                    mma16816h(lacc[fm][2 * bi + 1], al[fm], bf + 2);
                }
            }
        }
        __syncthreads();
    }

    // ---- fused epilogue (per-fragment section) ----
    const int r0 = lane >> 2;
    const int c0 = (lane & 3) * 2;
#pragma unroll
    for (int fm = 0; fm < 4; fm++) {
        const int row = mBase + wm * 64 + fm * 16 + r0;
        const int t0 = row & (TT - 1);
        const int t1 = (row + 8) & (TT - 1);
#pragma unroll
        for (int fn = 0; fn < 6; fn++) {
            float v[4] = {acc[fm][fn][0], acc[fm][fn][1],
                          acc[fm][fn][2], acc[fm][fn][3]};
            merge_lo(v, lacc[fm][fn]);
            const int col = nBase + wn * 48 + fn * 8 + c0;
            const int sec = col >> 11;
            const int cloc = col & (N_EMBD - 1);
            if (sec < 2) {
                const int i0 = (cloc & 127) >> 1;
                float cA = g_cos[t0 * 64 + i0], sA = g_sin[t0 * 64 + i0];
                float cB = g_cos[t1 * 64 + i0], sB = g_sin[t1 * 64 + i0];
                float r00 = v[0] * cA - v[1] * sA, r01 = v[1] * cA + v[0] * sA;
                float r10 = v[2] * cB - v[3] * sB, r11 = v[3] * cB + v[2] * sB;
                if (sec == 0) {
                    uint32_t h0, l0, h1, l1;
                    pack_hl(r00, r01, h0, l0);
                    pack_hl(r10, r11, h1, l1);
                    *(uint32_t*)(Qh + (size_t)row * N_EMBD + cloc) = h0;
                    *(uint32_t*)(Ql + (size_t)row * N_EMBD + cloc) = l0;
                    *(uint32_t*)(Qh + (size_t)(row + 8) * N_EMBD + cloc) = h1;
                    *(uint32_t*)(Ql + (size_t)(row + 8) * N_EMBD + cloc) = l1;
                } else {
                    *(__half2*)(Kb + (size_t)row * N_EMBD + cloc) =
                        __floats2half2_rn(r00, r01);
                    *(__half2*)(Kb + (size_t)(row + 8) * N_EMBD + cloc) =
                        __floats2half2_rn(r10, r11);
                }
            } else {
                *(__half2*)(Vh + (size_t)row * N_EMBD + cloc) =
                    __floats2half2_rn(v[0], v[1]);
                *(__half2*)(Vh + (size_t)(row + 8) * N_EMBD + cloc) =
                    __floats2half2_rn(v[2], v[3]);
            }
        }
    }
}

// ---------------------------------------------------------------------------
// Proj GEMM (BN=128): hi fp32-acc + lo fp16-acc, fp32 out.
// ---------------------------------------------------------------------------
__global__ __launch_bounds__(256, 1) void gemm_proj_kernel(
    const __half* __restrict__ Ah, const __half* __restrict__ Al,
    const __half* __restrict__ B,
    float* __restrict__ C, int M, int N, int K)
{
    extern __shared__ char smc[];
    const uint32_t sbase = smem_u32(smc);
    const int tid = threadIdx.x;
    const int lane = tid & 31;
    const int wid = tid >> 5;
    const int wm = wid & 1;
    const int wn = wid >> 1;           // 4 warps x 32 cols
    const int mBase = blockIdx.y * BM;
    const int nBase = blockIdx.x * BN4;
    const int nch = K / BK;

    const int ldRow = tid >> 2;
    const int ldCh  = tid & 3;

    float acc[4][4][4];
    uint32_t lacc[4][4][2];
#pragma unroll
    for (int i = 0; i < 4; i++)
#pragma unroll
        for (int j = 0; j < 4; j++) {
#pragma unroll
            for (int r = 0; r < 4; r++) acc[i][j][r] = 0.0f;
            lacc[i][j][0] = 0u; lacc[i][j][1] = 0u;
        }

    auto issue_stage = [&](int c, int buf) {
        const uint32_t st = sbase + buf * STG4;
        const int kOff = c * BK;
#pragma unroll
        for (int i = 0; i < 2; i++) {
            const int row = i * 64 + ldRow;
            const uint32_t so = row * PADB + ldCh * 16;
            CP_ASYNC16(st + so,
                       Ah + (size_t)(mBase + row) * K + kOff + ldCh * 8);
            CP_ASYNC16(st + A_BYTES + so,
                       Al + (size_t)(mBase + row) * K + kOff + ldCh * 8);
        }
#pragma unroll
        for (int i = 0; i < 2; i++) {
            const int row = i * 64 + ldRow;
            const uint32_t so = row * PADB + ldCh * 16;
            CP_ASYNC16(st + 2 * A_BYTES + so,
                       B + (size_t)(nBase + row) * K + kOff + ldCh * 8);
        }
    };

    issue_stage(0, 0);
    CP_COMMIT();

    const int arow = (lane & 7) + ((lane >> 3) & 1) * 8;
    const int akc8 = (lane >> 4) * 8;
    const int brow = (lane & 7) + ((lane >> 4) & 1) * 8;
    const int bkc8 = ((lane >> 3) & 1) * 8;

    for (int c = 0; c < nch; c++) {
        const int buf = c & 1;
        if (c + 1 < nch) issue_stage(c + 1, (c + 1) & 1);
        CP_COMMIT();
        CP_WAIT1();
        __syncthreads();

        const uint32_t st = sbase + buf * STG4;
        const uint32_t ahB = st;
        const uint32_t alB = st + A_BYTES;
        const uint32_t bB  = st + 2 * A_BYTES;

#pragma unroll
        for (int s = 0; s < 2; s++) {
            const int kofs = s * 16;
            uint32_t ah[4][4], al[4][4];
#pragma unroll
            for (int fm = 0; fm < 4; fm++) {
                const uint32_t off =
                    (uint32_t)((wm * 64 + fm * 16 + arow) * PADB +
                               (kofs + akc8) * 2);
                ldsm_x4(ah[fm], ahB + off);
                ldsm_x4(al[fm], alB + off);
            }
#pragma unroll
            for (int bi = 0; bi < 2; bi++) {
                uint32_t bf[4];
                const uint32_t off =
                    (uint32_t)((wn * 32 + bi * 16 + brow) * PADB +
                               (kofs + bkc8) * 2);
                ldsm_x4(bf, bB + off);
#pragma unroll
                for (int fm = 0; fm < 4; fm++) {
                    mma16816(acc[fm][2 * bi],     ah[fm], bf);
                    mma16816(acc[fm][2 * bi + 1], ah[fm], bf + 2);
                }
#pragma unroll
                for (int fm = 0; fm < 4; fm++) {
                    mma16816h(lacc[fm][2 * bi],     al[fm], bf);
                    mma16816h(lacc[fm][2 * bi + 1], al[fm], bf + 2);
                }
            }
        }
        __syncthreads();
    }

    const int r0 = lane >> 2;
    const int c0 = (lane & 3) * 2;
#pragma unroll
    for (int fm = 0; fm < 4; fm++) {
#pragma unroll
        for (int fn = 0; fn < 4; fn++) {
            float v[4] = {acc[fm][fn][0], acc[fm][fn][1],
                          acc[fm][fn][2], acc[fm][fn][3]};
            merge_lo(v, lacc[fm][fn]);
            const size_t row = (size_t)(mBase + wm * 64 + fm * 16 + r0);
            const int col = nBase + wn * 32 + fn * 8 + c0;
            *(float2*)(C + row * N + col) = make_float2(v[0], v[1]);
            *(float2*)(C + (row + 8) * N + col) = make_float2(v[2], v[3]);
        }
    }
}

// ---------------------------------------------------------------------------
// Flash attention: hi-terms fp32-acc, lo-terms fp16-acc (per key tile).
// ---------------------------------------------------------------------------
#define FQ_BYTES   (128 * 272)
#define FK_BYTES   (64 * 272)
#define FV_BYTES   (128 * 144)
#define FSTAGE     (FK_BYTES + FV_BYTES)
#define FQ_TOTAL   (2 * FQ_BYTES)
#define FA_SMEM    (FQ_TOTAL + 2 * FSTAGE)

__global__ __launch_bounds__(256, 1) void flash_mma_kernel(
    const __half* __restrict__ qh, const __half* __restrict__ ql,
    const __half* __restrict__ kh, const __half* __restrict__ vt,
    __half* __restrict__ yh, __half* __restrict__ yl)
{
    extern __shared__ char smc[];
    const uint32_t sbase = smem_u32(smc);
    const int tid = threadIdx.x;
    const int lane = tid & 31;
    const int wid = tid >> 5;
    const int b = blockIdx.z, h = blockIdx.y;
    const int bh = b * NH + h;
    const int q0 = blockIdx.x * 128;
    const size_t bT = (size_t)b * TT;
    const int hoff = h * HD;

    {
#pragma unroll
        for (int i = 0; i < 8; i++) {
            int cid = i * 256 + tid;
            int row = cid >> 4, ch = cid & 15;
            CP_ASYNC16(sbase + row * 272 + ch * 16,
                       qh + (bT + q0 + row) * N_EMBD + hoff + ch * 8);
            CP_ASYNC16(sbase + FQ_BYTES + row * 272 + ch * 16,
                       ql + (bT + q0 + row) * N_EMBD + hoff + ch * 8);
        }
        CP_COMMIT();
    }

    auto issue_stage = [&](int it, int buf) {
        const uint32_t st = sbase + FQ_TOTAL + buf * FSTAGE;
        const int n0 = it * 64;
#pragma unroll
        for (int i = 0; i < 4; i++) {
            int cid = i * 256 + tid;
            int row = cid >> 4, ch = cid & 15;
            CP_ASYNC16(st + row * 272 + ch * 16,
                       kh + (bT + n0 + row) * N_EMBD + hoff + ch * 8);
        }
#pragma unroll
        for (int i = 0; i < 4; i++) {
            int cid = i * 256 + tid;
            int row = cid >> 3, ch = cid & 7;
            CP_ASYNC16(st + FK_BYTES + row * 144 + ch * 16,
                       vt + (size_t)(bh * HD + row) * TT + n0 + ch * 8);
        }
    };

    issue_stage(0, 0);
    CP_COMMIT();

    const int arow = (lane & 7) + ((lane >> 3) & 1) * 8;
    const int aoff = (lane >> 4) * 16;
    const int brow = (lane & 7) + ((lane >> 4) & 1) * 8;
    const int boff = ((lane >> 3) & 1) * 16;
    const int g = lane >> 2;
    const int tq = lane & 3;

    float O[16][4];
#pragma unroll
    for (int i = 0; i < 16; i++)
#pragma unroll
        for (int r = 0; r < 4; r++) O[i][r] = 0.0f;
    float ma = -INFINITY, mb = -INFINITY, la = 0.0f, lb = 0.0f;
    const float sc = 0.08838834764831845f;

    const int niter = TT / 64;
    for (int c = 0; c < niter; c++) {
        const int buf = c & 1;
        if (c + 1 < niter) issue_stage(c + 1, (c + 1) & 1);
        CP_COMMIT();
        CP_WAIT1();
        __syncthreads();

        const uint32_t kb = sbase + FQ_TOTAL + buf * FSTAGE;

        float s[8][4];
        uint32_t slo[8][2];
#pragma unroll
        for (int j = 0; j < 8; j++) {
#pragma unroll
            for (int r = 0; r < 4; r++) s[j][r] = 0.0f;
            slo[j][0] = 0u; slo[j][1] = 0u;
        }

#pragma unroll
        for (int kk = 0; kk < 8; kk++) {
            uint32_t qf[4], qlf[4];
            const uint32_t qo = (wid * 16 + arow) * 272 + kk * 32 + aoff;
            ldsm_x4(qf, sbase + qo);
            ldsm_x4(qlf, sbase + FQ_BYTES + qo);
#pragma unroll
            for (int bp = 0; bp < 2; bp++) {
                uint32_t khf[2][4];
#pragma unroll
                for (int u = 0; u < 2; u++) {
                    const int bi = 2 * bp + u;
                    const uint32_t ko = (bi * 16 + brow) * 272 + kk * 32 + boff;
                    ldsm_x4(khf[u], kb + ko);
                }
#pragma unroll
                for (int u = 0; u < 2; u++) {
                    const int bi = 2 * bp + u;
                    mma16816(s[2 * bi],     qf, khf[u]);
                    mma16816(s[2 * bi + 1], qf, khf[u] + 2);
                }
#pragma unroll
                for (int u = 0; u < 2; u++) {
                    const int bi = 2 * bp + u;
                    mma16816h(slo[2 * bi],     qlf, khf[u]);
                    mma16816h(slo[2 * bi + 1], qlf, khf[u] + 2);
                }
            }
        }
#pragma unroll
        for (int j = 0; j < 8; j++) merge_lo(s[j], slo[j]);

        float mxa = -INFINITY, mxb = -INFINITY;
#pragma unroll
        for (int j = 0; j < 8; j++) {
            s[j][0] *= sc; s[j][1] *= sc; s[j][2] *= sc; s[j][3] *= sc;
            mxa = fmaxf(mxa, fmaxf(s[j][0], s[j][1]));
            mxb = fmaxf(mxb, fmaxf(s[j][2], s[j][3]));
        }
        mxa = fmaxf(mxa, __shfl_xor_sync(0xffffffffu, mxa, 1));
        mxa = fmaxf(mxa, __shfl_xor_sync(0xffffffffu, mxa, 2));
        mxb = fmaxf(mxb, __shfl_xor_sync(0xffffffffu, mxb, 1));
        mxb = fmaxf(mxb, __shfl_xor_sync(0xffffffffu, mxb, 2));
        float mna = fmaxf(ma, mxa), mnb = fmaxf(mb, mxb);
        float alpha = __expf(ma - mna), beta = __expf(mb - mnb);
        ma = mna; mb = mnb;
        float sua = 0.0f, sub = 0.0f;
#pragma unroll
        for (int j = 0; j < 8; j++) {
            s[j][0] = __expf(s[j][0] - mna);
            s[j][1] = __expf(s[j][1] - mna);
            s[j][2] = __expf(s[j][2] - mnb);
            s[j][3] = __expf(s[j][3] - mnb);
            sua += s[j][0] + s[j][1];
            sub += s[j][2] + s[j][3];
        }
        sua += __shfl_xor_sync(0xffffffffu, sua, 1);
        sua += __shfl_xor_sync(0xffffffffu, sua, 2);
        sub += __shfl_xor_sync(0xffffffffu, sub, 1);
        sub += __shfl_xor_sync(0xffffffffu, sub, 2);
        la = la * alpha + sua;
        lb = lb * beta + sub;
#pragma unroll
        for (int j2 = 0; j2 < 16; j2++) {
            O[j2][0] *= alpha; O[j2][1] *= alpha;
            O[j2][2] *= beta;  O[j2][3] *= beta;
        }

        uint32_t Ph[4][4], Pl[4][4];
#pragma unroll
        for (int kp = 0; kp < 4; kp++) {
            pack_hl(s[2 * kp][0],     s[2 * kp][1],     Ph[kp][0], Pl[kp][0]);
            pack_hl(s[2 * kp][2],     s[2 * kp][3],     Ph[kp][1], Pl[kp][1]);
            pack_hl(s[2 * kp + 1][0], s[2 * kp + 1][1], Ph[kp][2], Pl[kp][2]);
            pack_hl(s[2 * kp + 1][2], s[2 * kp + 1][3], Ph[kp][3], Pl[kp][3]);
        }

        // O += Ph@V (fp32 acc) + Pl@V (fp16 acc, merged per tile)
        uint32_t olo[16][2];
#pragma unroll
        for (int j2 = 0; j2 < 16; j2++) { olo[j2][0] = 0u; olo[j2][1] = 0u; }

        const uint32_t vb = kb + FK_BYTES;
#pragma unroll
        for (int kp = 0; kp < 4; kp++) {
#pragma unroll
            for (int jp = 0; jp < 4; jp++) {
                uint32_t vhf[2][4];
#pragma unroll
                for (int u = 0; u < 2; u++) {
                    const int j4 = 2 * jp + u;
                    const uint32_t vo = (j4 * 16 + brow) * 144 + kp * 32 + boff;
                    ldsm_x4(vhf[u], vb + vo);
                }
#pragma unroll
                for (int u = 0; u < 2; u++) {
                    const int j4 = 2 * jp + u;
                    mma16816(O[2 * j4],     Ph[kp], vhf[u]);
                    mma16816(O[2 * j4 + 1], Ph[kp], vhf[u] + 2);
                }
#pragma unroll
                for (int u = 0; u < 2; u++) {
                    const int j4 = 2 * jp + u;
                    mma16816h(olo[2 * j4],     Pl[kp], vhf[u]);
                    mma16816h(olo[2 * j4 + 1], Pl[kp], vhf[u] + 2);
                }
            }
        }
#pragma unroll
        for (int j2 = 0; j2 < 16; j2++) merge_lo(O[j2], olo[j2]);
        __syncthreads();
    }

    const float inva = 1.0f / la, invb = 1.0f / lb;
    const size_t rowa = bT + q0 + wid * 16 + g;
    const size_t rowb = rowa + 8;
#pragma unroll
    for (int j2 = 0; j2 < 16; j2++) {
        const int col = hoff + j2 * 8 + tq * 2;
        uint32_t h0, l0, h1, l1;
        pack_hl(O[j2][0] * inva, O[j2][1] * inva, h0, l0);
        pack_hl(O[j2][2] * invb, O[j2][3] * invb, h1, l1);
        *(uint32_t*)(yh + rowa * N_EMBD + col) = h0;
        *(uint32_t*)(yl + rowa * N_EMBD + col) = l0;
        *(uint32_t*)(yh + rowb * N_EMBD + col) = h1;
        *(uint32_t*)(yl + rowb * N_EMBD + col) = l1;
    }
}

// ---------------------------------------------------------------------------
// Launch
// ---------------------------------------------------------------------------
extern "C" void kernel_launch(void* const* d_in, const int* in_sizes, int n_in,
                              void* d_out, int out_size)
{
    const float* x      = (const float*)d_in[0];
    const float* w_attn = (const float*)d_in[1];
    const float* w_proj = (const float*)d_in[2];
    float* out = (float*)d_out;

    __half *Ah, *Al, *Wa, *Wp, *Qh, *Ql, *Kb, *Vh, *Vt;
    cudaGetSymbolAddress((void**)&Ah, g_Ah);
    cudaGetSymbolAddress((void**)&Al, g_Al);
    cudaGetSymbolAddress((void**)&Wa, g_Wa);
    cudaGetSymbolAddress((void**)&Wp, g_Wp);
    cudaGetSymbolAddress((void**)&Qh, g_Qh);
    cudaGetSymbolAddress((void**)&Ql, g_Ql);
    cudaGetSymbolAddress((void**)&Kb, g_K);
    cudaGetSymbolAddress((void**)&Vh, g_Vh);
    cudaGetSymbolAddress((void**)&Vt, g_Vt);

    cudaFuncSetAttribute(gemm_qkv_kernel,
                         cudaFuncAttributeMaxDynamicSharedMemorySize, QKV_SMEM);
    cudaFuncSetAttribute(gemm_proj_kernel,
                         cudaFuncAttributeMaxDynamicSharedMemorySize, PROJ_SMEM);
    cudaFuncSetAttribute(flash_mma_kernel,
                         cudaFuncAttributeMaxDynamicSharedMemorySize, FA_SMEM);

    const int n4 = MROWS * N_EMBD / 4;

    rope_table_kernel<<<(TT * 64 + 255) / 256, 256>>>();

    conv_rm_kernel<<<(n4 + 255) / 256, 256>>>(x, Ah, Al, n4);
    conv_tr_kernel<<<dim3(QKV_N / 32, N_EMBD / 32), dim3(32, 8)>>>(
        w_attn, Wa, N_EMBD, QKV_N);
    conv_tr_kernel<<<dim3(N_EMBD / 32, N_EMBD / 32), dim3(32, 8)>>>(
        w_proj, Wp, N_EMBD, N_EMBD);

    // QKV projection (BN=192 -> 1024 CTAs, 98.8% wave efficiency)
    gemm_qkv_kernel<<<dim3(QKV_N / BN6, MROWS / BM), 256, QKV_SMEM>>>(
        Ah, Al, Wa, Qh, Ql, Kb, Vh);

    conv_vth_kernel<<<dim3(TT / 32, HD / 32, BB * NH), dim3(32, 8)>>>(Vh, Vt);

    flash_mma_kernel<<<dim3(TT / 128, NH, BB), 256, FA_SMEM>>>(
        Qh, Ql, Kb, Vt, Ah, Al);

    gemm_proj_kernel<<<dim3(N_EMBD / BN4, MROWS / BM), 256, PROJ_SMEM>>>(
        Ah, Al, Wp, out, MROWS, N_EMBD, N_EMBD);
}

// round 13
// speedup vs baseline: 1.0599x; 1.0599x over previous
#include <cuda_runtime.h>
#include <cuda_fp16.h>
#include <stdint.h>
#include <math.h>

// ---------------------------------------------------------------------------
// Problem constants
// ---------------------------------------------------------------------------
#define N_EMBD 2048
#define NH     16
#define HD     128
#define TT     2048
#define BB     2
#define MROWS  (BB * TT)
#define QKV_N  (3 * N_EMBD)

// ---------------------------------------------------------------------------
// Scratch
// ---------------------------------------------------------------------------
__device__ float g_cos[TT * (HD / 2)];
__device__ float g_sin[TT * (HD / 2)];
__device__ __half g_Ah[(size_t)MROWS * N_EMBD];   // x-hi, later y-hi
__device__ __half g_Al[(size_t)MROWS * N_EMBD];   // x-lo, later y-lo
__device__ __half g_Wa[(size_t)QKV_N * N_EMBD];
__device__ __half g_Wp[(size_t)N_EMBD * N_EMBD];
__device__ __half g_Qh[(size_t)MROWS * N_EMBD];
__device__ __half g_Ql[(size_t)MROWS * N_EMBD];
__device__ __half g_K [(size_t)MROWS * N_EMBD];
__device__ __half g_Vh[(size_t)MROWS * N_EMBD];
__device__ __half g_Vt[(size_t)MROWS * N_EMBD];

// ---------------------------------------------------------------------------
// Helpers
// ---------------------------------------------------------------------------
__device__ __forceinline__ uint32_t smem_u32(const void* p) {
    uint32_t a;
    asm("{ .reg .u64 t; cvta.to.shared.u64 t, %1; cvt.u32.u64 %0, t; }"
        : "=r"(a) : "l"(p));
    return a;
}

__device__ __forceinline__ void ldsm_x4(uint32_t* r, uint32_t addr) {
    asm volatile("ldmatrix.sync.aligned.m8n8.x4.shared.b16 {%0,%1,%2,%3}, [%4];"
                 : "=r"(r[0]), "=r"(r[1]), "=r"(r[2]), "=r"(r[3]) : "r"(addr));
}

__device__ __forceinline__ void mma16816(float* c, const uint32_t* a,
                                         const uint32_t* b) {
    asm volatile(
        "mma.sync.aligned.m16n8k16.row.col.f32.f16.f16.f32 "
        "{%0,%1,%2,%3}, {%4,%5,%6,%7}, {%8,%9}, {%0,%1,%2,%3};"
        : "+f"(c[0]), "+f"(c[1]), "+f"(c[2]), "+f"(c[3])
        : "r"(a[0]), "r"(a[1]), "r"(a[2]), "r"(a[3]), "r"(b[0]), "r"(b[1]));
}

#define CP_ASYNC16(dst, src) \
    asm volatile("cp.async.cg.shared.global [%0], [%1], 16;" \
                 :: "r"(dst), "l"(src) : "memory")
#define CP_COMMIT() asm volatile("cp.async.commit_group;" ::: "memory")
#define CP_WAIT1()  asm volatile("cp.async.wait_group 1;" ::: "memory")

__device__ __forceinline__ void pack_hl(float x, float y, uint32_t& h, uint32_t& l) {
    __half2 hh = __floats2half2_rn(x, y);
    float rx = x - __half2float(__low2half(hh));
    float ry = y - __half2float(__high2half(hh));
    __half2 ll = __floats2half2_rn(rx, ry);
    h = *(uint32_t*)&hh;
    l = *(uint32_t*)&ll;
}

// ---------------------------------------------------------------------------
// Convert kernels
// ---------------------------------------------------------------------------
__global__ void conv_rm_kernel(const float* __restrict__ in,
                               __half* __restrict__ oh,
                               __half* __restrict__ ol, int n4) {
    int idx = blockIdx.x * blockDim.x + threadIdx.x;
    if (idx >= n4) return;
    float4 v = ((const float4*)in)[idx];
    __half2 h01 = __floats2half2_rn(v.x, v.y);
    __half2 h23 = __floats2half2_rn(v.z, v.w);
    __half2 l01 = __floats2half2_rn(v.x - __half2float(__low2half(h01)),
                                    v.y - __half2float(__high2half(h01)));
    __half2 l23 = __floats2half2_rn(v.z - __half2float(__low2half(h23)),
                                    v.w - __half2float(__high2half(h23)));
    ((__half2*)oh)[idx * 2]     = h01;
    ((__half2*)oh)[idx * 2 + 1] = h23;
    ((__half2*)ol)[idx * 2]     = l01;
    ((__half2*)ol)[idx * 2 + 1] = l23;
}

__global__ void conv_tr_kernel(const float* __restrict__ B,
                               __half* __restrict__ bt, int K, int N) {
    __shared__ float tile[32][33];
    int n0 = blockIdx.x * 32, k0 = blockIdx.y * 32;
    int tx = threadIdx.x, ty = threadIdx.y;
#pragma unroll
    for (int i = 0; i < 4; i++)
        tile[ty + i * 8][tx] = B[(size_t)(k0 + ty + i * 8) * N + n0 + tx];
    __syncthreads();
#pragma unroll
    for (int i = 0; i < 4; i++) {
        int n = ty + i * 8;
        bt[(size_t)(n0 + n) * K + k0 + tx] = __float2half_rn(tile[tx][n]);
    }
}

__global__ void conv_vth_kernel(const __half* __restrict__ vh,
                                __half* __restrict__ vt) {
    __shared__ __half tile[32][34];
    int bh = blockIdx.z;
    int b = bh >> 4, h = bh & 15;
    int t0 = blockIdx.x * 32, d0 = blockIdx.y * 32;
    int tx = threadIdx.x, ty = threadIdx.y;
#pragma unroll
    for (int i = 0; i < 4; i++)
        tile[ty + i * 8][tx] =
            vh[(size_t)(b * TT + t0 + ty + i * 8) * N_EMBD + h * HD + d0 + tx];
    __syncthreads();
#pragma unroll
    for (int i = 0; i < 4; i++) {
        int d = ty + i * 8;
        vt[(size_t)(bh * HD + d0 + d) * TT + t0 + tx] = tile[tx][d];
    }
}

__global__ void rope_table_kernel() {
    int idx = blockIdx.x * blockDim.x + threadIdx.x;
    if (idx >= TT * 64) return;
    int t = idx >> 6;
    int i = idx & 63;
    double theta = pow(10000.0, -(double)i / 64.0);
    double ang = (double)t * theta;
    g_cos[idx] = (float)cos(ang);
    g_sin[idx] = (float)sin(ang);
}

// ---------------------------------------------------------------------------
// GEMM config
// ---------------------------------------------------------------------------
#define BM 128
#define BK 32
#define PADB 80
#define A_BYTES (128 * PADB)

// QKV: BN=192 -> 1024 CTAs -> 98.8% wave efficiency
#define BN6 192
#define B6_BYTES (192 * PADB)
#define STG6 (2 * A_BYTES + B6_BYTES)            // 35840
#define QKV_SMEM (2 * STG6)                      // 71680

// Proj: BN=256 (R10 config)
#define BN4 256
#define B4_BYTES (256 * PADB)
#define STG4 (2 * A_BYTES + B4_BYTES)            // 40960
#define PROJ_SMEM (2 * STG4)                     // 81920

// ---------------------------------------------------------------------------
// QKV GEMM (BN=192, fp32-acc 2-term) with fused RoPE/convert epilogue.
// ---------------------------------------------------------------------------
__global__ __launch_bounds__(256, 1) void gemm_qkv_kernel(
    const __half* __restrict__ Ah, const __half* __restrict__ Al,
    const __half* __restrict__ B,
    __half* __restrict__ Qh, __half* __restrict__ Ql,
    __half* __restrict__ Kb, __half* __restrict__ Vh)
{
    const int K = N_EMBD;
    extern __shared__ char smc[];
    const uint32_t sbase = smem_u32(smc);
    const int tid = threadIdx.x;
    const int lane = tid & 31;
    const int wid = tid >> 5;
    const int wm = wid & 1;            // 2 warps in M (64 rows)
    const int wn = wid >> 1;           // 4 warps in N (48 cols)
    const int mBase = blockIdx.y * BM;
    const int nBase = blockIdx.x * BN6;
    const int nch = K / BK;

    const int ldRow = tid >> 2;
    const int ldCh  = tid & 3;

    float acc[4][6][4];
#pragma unroll
    for (int i = 0; i < 4; i++)
#pragma unroll
        for (int j = 0; j < 6; j++)
#pragma unroll
            for (int r = 0; r < 4; r++) acc[i][j][r] = 0.0f;

    auto issue_stage = [&](int c, int buf) {
        const uint32_t st = sbase + buf * STG6;
        const int kOff = c * BK;
#pragma unroll
        for (int i = 0; i < 2; i++) {
            const int row = i * 64 + ldRow;
            const uint32_t so = row * PADB + ldCh * 16;
            CP_ASYNC16(st + so,
                       Ah + (size_t)(mBase + row) * K + kOff + ldCh * 8);
            CP_ASYNC16(st + A_BYTES + so,
                       Al + (size_t)(mBase + row) * K + kOff + ldCh * 8);
        }
#pragma unroll
        for (int i = 0; i < 3; i++) {
            const int row = i * 64 + ldRow;
            const uint32_t so = row * PADB + ldCh * 16;
            CP_ASYNC16(st + 2 * A_BYTES + so,
                       B + (size_t)(nBase + row) * K + kOff + ldCh * 8);
        }
    };

    issue_stage(0, 0);
    CP_COMMIT();

    const int arow = (lane & 7) + ((lane >> 3) & 1) * 8;
    const int akc8 = (lane >> 4) * 8;
    const int brow = (lane & 7) + ((lane >> 4) & 1) * 8;
    const int bkc8 = ((lane >> 3) & 1) * 8;

    for (int c = 0; c < nch; c++) {
        const int buf = c & 1;
        if (c + 1 < nch) issue_stage(c + 1, (c + 1) & 1);
        CP_COMMIT();
        CP_WAIT1();
        __syncthreads();

        const uint32_t st = sbase + buf * STG6;
        const uint32_t ahB = st;
        const uint32_t alB = st + A_BYTES;
        const uint32_t bB  = st + 2 * A_BYTES;

#pragma unroll
        for (int s = 0; s < 2; s++) {
            const int kofs = s * 16;
            uint32_t ah[4][4], al[4][4];
#pragma unroll
            for (int fm = 0; fm < 4; fm++) {
                const uint32_t off =
                    (uint32_t)((wm * 64 + fm * 16 + arow) * PADB +
                               (kofs + akc8) * 2);
                ldsm_x4(ah[fm], ahB + off);
                ldsm_x4(al[fm], alB + off);
            }
#pragma unroll
            for (int bi = 0; bi < 3; bi++) {
                uint32_t bf[4];
                const uint32_t off =
                    (uint32_t)((wn * 48 + bi * 16 + brow) * PADB +
                               (kofs + bkc8) * 2);
                ldsm_x4(bf, bB + off);
#pragma unroll
                for (int fm = 0; fm < 4; fm++) {
                    mma16816(acc[fm][2 * bi],     ah[fm], bf);
                    mma16816(acc[fm][2 * bi + 1], ah[fm], bf + 2);
                }
#pragma unroll
                for (int fm = 0; fm < 4; fm++) {
                    mma16816(acc[fm][2 * bi],     al[fm], bf);
                    mma16816(acc[fm][2 * bi + 1], al[fm], bf + 2);
                }
            }
        }
        __syncthreads();
    }

    // ---- fused epilogue (per-fragment section since 192 !| 2048) ----
    const int r0 = lane >> 2;
    const int c0 = (lane & 3) * 2;
#pragma unroll
    for (int fm = 0; fm < 4; fm++) {
        const int row = mBase + wm * 64 + fm * 16 + r0;
        const int t0 = row & (TT - 1);
        const int t1 = (row + 8) & (TT - 1);
#pragma unroll
        for (int fn = 0; fn < 6; fn++) {
            const float v0 = acc[fm][fn][0], v1 = acc[fm][fn][1];
            const float v2 = acc[fm][fn][2], v3 = acc[fm][fn][3];
            const int col = nBase + wn * 48 + fn * 8 + c0;
            const int sec = col >> 11;
            const int cloc = col & (N_EMBD - 1);
            if (sec < 2) {
                const int i0 = (cloc & 127) >> 1;
                float cA = g_cos[t0 * 64 + i0], sA = g_sin[t0 * 64 + i0];
                float cB = g_cos[t1 * 64 + i0], sB = g_sin[t1 * 64 + i0];
                float r00 = v0 * cA - v1 * sA, r01 = v1 * cA + v0 * sA;
                float r10 = v2 * cB - v3 * sB, r11 = v3 * cB + v2 * sB;
                if (sec == 0) {
                    uint32_t h0, l0, h1, l1;
                    pack_hl(r00, r01, h0, l0);
                    pack_hl(r10, r11, h1, l1);
                    *(uint32_t*)(Qh + (size_t)row * N_EMBD + cloc) = h0;
                    *(uint32_t*)(Ql + (size_t)row * N_EMBD + cloc) = l0;
                    *(uint32_t*)(Qh + (size_t)(row + 8) * N_EMBD + cloc) = h1;
                    *(uint32_t*)(Ql + (size_t)(row + 8) * N_EMBD + cloc) = l1;
                } else {
                    *(__half2*)(Kb + (size_t)row * N_EMBD + cloc) =
                        __floats2half2_rn(r00, r01);
                    *(__half2*)(Kb + (size_t)(row + 8) * N_EMBD + cloc) =
                        __floats2half2_rn(r10, r11);
                }
            } else {
                *(__half2*)(Vh + (size_t)row * N_EMBD + cloc) =
                    __floats2half2_rn(v0, v1);
                *(__half2*)(Vh + (size_t)(row + 8) * N_EMBD + cloc) =
                    __floats2half2_rn(v2, v3);
            }
        }
    }
}

// ---------------------------------------------------------------------------
// Proj GEMM (BN=256, R10 config): fp32 out
// ---------------------------------------------------------------------------
__global__ __launch_bounds__(256, 1) void gemm_proj_kernel(
    const __half* __restrict__ Ah, const __half* __restrict__ Al,
    const __half* __restrict__ B,
    float* __restrict__ C, int M, int N, int K)
{
    extern __shared__ char smc[];
    const uint32_t sbase = smem_u32(smc);
    const int tid = threadIdx.x;
    const int lane = tid & 31;
    const int wid = tid >> 5;
    const int wm = wid & 1;
    const int wn = wid >> 1;
    const int mBase = blockIdx.y * BM;
    const int nBase = blockIdx.x * BN4;
    const int nch = K / BK;

    const int ldRow = tid >> 2;
    const int ldCh  = tid & 3;

    float acc[4][8][4];
#pragma unroll
    for (int i = 0; i < 4; i++)
#pragma unroll
        for (int j = 0; j < 8; j++)
#pragma unroll
            for (int r = 0; r < 4; r++) acc[i][j][r] = 0.0f;

    auto issue_stage = [&](int c, int buf) {
        const uint32_t st = sbase + buf * STG4;
        const int kOff = c * BK;
#pragma unroll
        for (int i = 0; i < 2; i++) {
            const int row = i * 64 + ldRow;
            const uint32_t so = row * PADB + ldCh * 16;
            CP_ASYNC16(st + so,
                       Ah + (size_t)(mBase + row) * K + kOff + ldCh * 8);
            CP_ASYNC16(st + A_BYTES + so,
                       Al + (size_t)(mBase + row) * K + kOff + ldCh * 8);
        }
#pragma unroll
        for (int i = 0; i < 4; i++) {
            const int row = i * 64 + ldRow;
            const uint32_t so = row * PADB + ldCh * 16;
            CP_ASYNC16(st + 2 * A_BYTES + so,
                       B + (size_t)(nBase + row) * K + kOff + ldCh * 8);
        }
    };

    issue_stage(0, 0);
    CP_COMMIT();

    const int arow = (lane & 7) + ((lane >> 3) & 1) * 8;
    const int akc8 = (lane >> 4) * 8;
    const int brow = (lane & 7) + ((lane >> 4) & 1) * 8;
    const int bkc8 = ((lane >> 3) & 1) * 8;

    for (int c = 0; c < nch; c++) {
        const int buf = c & 1;
        if (c + 1 < nch) issue_stage(c + 1, (c + 1) & 1);
        CP_COMMIT();
        CP_WAIT1();
        __syncthreads();

        const uint32_t st = sbase + buf * STG4;
        const uint32_t ahB = st;
        const uint32_t alB = st + A_BYTES;
        const uint32_t bB  = st + 2 * A_BYTES;

#pragma unroll
        for (int s = 0; s < 2; s++) {
            const int kofs = s * 16;
            uint32_t ah[4][4], al[4][4];
#pragma unroll
            for (int fm = 0; fm < 4; fm++) {
                const uint32_t off =
                    (uint32_t)((wm * 64 + fm * 16 + arow) * PADB +
                               (kofs + akc8) * 2);
                ldsm_x4(ah[fm], ahB + off);
                ldsm_x4(al[fm], alB + off);
            }
#pragma unroll
            for (int bi = 0; bi < 4; bi++) {
                uint32_t bf[4];
                const uint32_t off =
                    (uint32_t)((wn * 64 + bi * 16 + brow) * PADB +
                               (kofs + bkc8) * 2);
                ldsm_x4(bf, bB + off);
#pragma unroll
                for (int fm = 0; fm < 4; fm++) {
                    mma16816(acc[fm][2 * bi],     ah[fm], bf);
                    mma16816(acc[fm][2 * bi + 1], ah[fm], bf + 2);
                }
#pragma unroll
                for (int fm = 0; fm < 4; fm++) {
                    mma16816(acc[fm][2 * bi],     al[fm], bf);
                    mma16816(acc[fm][2 * bi + 1], al[fm], bf + 2);
                }
            }
        }
        __syncthreads();
    }

    const int r0 = lane >> 2;
    const int c0 = (lane & 3) * 2;
#pragma unroll
    for (int fm = 0; fm < 4; fm++) {
#pragma unroll
        for (int fn = 0; fn < 8; fn++) {
            const size_t row = (size_t)(mBase + wm * 64 + fm * 16 + r0);
            const int col = nBase + wn * 64 + fn * 8 + c0;
            *(float2*)(C + row * N + col) =
                make_float2(acc[fm][fn][0], acc[fm][fn][1]);
            *(float2*)(C + (row + 8) * N + col) =
                make_float2(acc[fm][fn][2], acc[fm][fn][3]);
        }
    }
}

// ---------------------------------------------------------------------------
// Flash attention (exact R10 version): fp16 2-term fp32-acc, epilogue
// writes split fp16 O into Ah/Al.
// ---------------------------------------------------------------------------
#define FQ_BYTES   (128 * 272)
#define FK_BYTES   (64 * 272)
#define FV_BYTES   (128 * 144)
#define FSTAGE     (FK_BYTES + FV_BYTES)
#define FQ_TOTAL   (2 * FQ_BYTES)
#define FA_SMEM    (FQ_TOTAL + 2 * FSTAGE)

__global__ __launch_bounds__(256, 1) void flash_mma_kernel(
    const __half* __restrict__ qh, const __half* __restrict__ ql,
    const __half* __restrict__ kh, const __half* __restrict__ vt,
    __half* __restrict__ yh, __half* __restrict__ yl)
{
    extern __shared__ char smc[];
    const uint32_t sbase = smem_u32(smc);
    const int tid = threadIdx.x;
    const int lane = tid & 31;
    const int wid = tid >> 5;
    const int b = blockIdx.z, h = blockIdx.y;
    const int bh = b * NH + h;
    const int q0 = blockIdx.x * 128;
    const size_t bT = (size_t)b * TT;
    const int hoff = h * HD;

    {
#pragma unroll
        for (int i = 0; i < 8; i++) {
            int cid = i * 256 + tid;
            int row = cid >> 4, ch = cid & 15;
            CP_ASYNC16(sbase + row * 272 + ch * 16,
                       qh + (bT + q0 + row) * N_EMBD + hoff + ch * 8);
            CP_ASYNC16(sbase + FQ_BYTES + row * 272 + ch * 16,
                       ql + (bT + q0 + row) * N_EMBD + hoff + ch * 8);
        }
        CP_COMMIT();
    }

    auto issue_stage = [&](int it, int buf) {
        const uint32_t st = sbase + FQ_TOTAL + buf * FSTAGE;
        const int n0 = it * 64;
#pragma unroll
        for (int i = 0; i < 4; i++) {
            int cid = i * 256 + tid;
            int row = cid >> 4, ch = cid & 15;
            CP_ASYNC16(st + row * 272 + ch * 16,
                       kh + (bT + n0 + row) * N_EMBD + hoff + ch * 8);
        }
#pragma unroll
        for (int i = 0; i < 4; i++) {
            int cid = i * 256 + tid;
            int row = cid >> 3, ch = cid & 7;
            CP_ASYNC16(st + FK_BYTES + row * 144 + ch * 16,
                       vt + (size_t)(bh * HD + row) * TT + n0 + ch * 8);
        }
    };

    issue_stage(0, 0);
    CP_COMMIT();

    const int arow = (lane & 7) + ((lane >> 3) & 1) * 8;
    const int aoff = (lane >> 4) * 16;
    const int brow = (lane & 7) + ((lane >> 4) & 1) * 8;
    const int boff = ((lane >> 3) & 1) * 16;
    const int g = lane >> 2;
    const int tq = lane & 3;

    float O[16][4];
#pragma unroll
    for (int i = 0; i < 16; i++)
#pragma unroll
        for (int r = 0; r < 4; r++) O[i][r] = 0.0f;
    float ma = -INFINITY, mb = -INFINITY, la = 0.0f, lb = 0.0f;
    const float sc = 0.08838834764831845f;

    const int niter = TT / 64;
    for (int c = 0; c < niter; c++) {
        const int buf = c & 1;
        if (c + 1 < niter) issue_stage(c + 1, (c + 1) & 1);
        CP_COMMIT();
        CP_WAIT1();
        __syncthreads();

        const uint32_t kb = sbase + FQ_TOTAL + buf * FSTAGE;

        float s[8][4];
#pragma unroll
        for (int j = 0; j < 8; j++)
#pragma unroll
            for (int r = 0; r < 4; r++) s[j][r] = 0.0f;

#pragma unroll
        for (int kk = 0; kk < 8; kk++) {
            uint32_t qf[4], qlf[4];
            const uint32_t qo = (wid * 16 + arow) * 272 + kk * 32 + aoff;
            ldsm_x4(qf, sbase + qo);
            ldsm_x4(qlf, sbase + FQ_BYTES + qo);
#pragma unroll
            for (int bp = 0; bp < 2; bp++) {
                uint32_t khf[2][4];
#pragma unroll
                for (int u = 0; u < 2; u++) {
                    const int bi = 2 * bp + u;
                    const uint32_t ko = (bi * 16 + brow) * 272 + kk * 32 + boff;
                    ldsm_x4(khf[u], kb + ko);
                }
#pragma unroll
                for (int u = 0; u < 2; u++) {
                    const int bi = 2 * bp + u;
                    mma16816(s[2 * bi],     qf, khf[u]);
                    mma16816(s[2 * bi + 1], qf, khf[u] + 2);
                }
#pragma unroll
                for (int u = 0; u < 2; u++) {
                    const int bi = 2 * bp + u;
                    mma16816(s[2 * bi],     qlf, khf[u]);
                    mma16816(s[2 * bi + 1], qlf, khf[u] + 2);
                }
            }
        }

        float mxa = -INFINITY, mxb = -INFINITY;
#pragma unroll
        for (int j = 0; j < 8; j++) {
            s[j][0] *= sc; s[j][1] *= sc; s[j][2] *= sc; s[j][3] *= sc;
            mxa = fmaxf(mxa, fmaxf(s[j][0], s[j][1]));
            mxb = fmaxf(mxb, fmaxf(s[j][2], s[j][3]));
        }
        mxa = fmaxf(mxa, __shfl_xor_sync(0xffffffffu, mxa, 1));
        mxa = fmaxf(mxa, __shfl_xor_sync(0xffffffffu, mxa, 2));
        mxb = fmaxf(mxb, __shfl_xor_sync(0xffffffffu, mxb, 1));
        mxb = fmaxf(mxb, __shfl_xor_sync(0xffffffffu, mxb, 2));
        float mna = fmaxf(ma, mxa), mnb = fmaxf(mb, mxb);
        float alpha = __expf(ma - mna), beta = __expf(mb - mnb);
        ma = mna; mb = mnb;
        float sua = 0.0f, sub = 0.0f;
#pragma unroll
        for (int j = 0; j < 8; j++) {
            s[j][0] = __expf(s[j][0] - mna);
            s[j][1] = __expf(s[j][1] - mna);
            s[j][2] = __expf(s[j][2] - mnb);
            s[j][3] = __expf(s[j][3] - mnb);
            sua += s[j][0] + s[j][1];
            sub += s[j][2] + s[j][3];
        }
        sua += __shfl_xor_sync(0xffffffffu, sua, 1);
        sua += __shfl_xor_sync(0xffffffffu, sua, 2);
        sub += __shfl_xor_sync(0xffffffffu, sub, 1);
        sub += __shfl_xor_sync(0xffffffffu, sub, 2);
        la = la * alpha + sua;
        lb = lb * beta + sub;
#pragma unroll
        for (int j2 = 0; j2 < 16; j2++) {
            O[j2][0] *= alpha; O[j2][1] *= alpha;
            O[j2][2] *= beta;  O[j2][3] *= beta;
        }

        uint32_t Ph[4][4], Pl[4][4];
#pragma unroll
        for (int kp = 0; kp < 4; kp++) {
            pack_hl(s[2 * kp][0],     s[2 * kp][1],     Ph[kp][0], Pl[kp][0]);
            pack_hl(s[2 * kp][2],     s[2 * kp][3],     Ph[kp][1], Pl[kp][1]);
            pack_hl(s[2 * kp + 1][0], s[2 * kp + 1][1], Ph[kp][2], Pl[kp][2]);
            pack_hl(s[2 * kp + 1][2], s[2 * kp + 1][3], Ph[kp][3], Pl[kp][3]);
        }

        const uint32_t vb = kb + FK_BYTES;
#pragma unroll
        for (int kp = 0; kp < 4; kp++) {
#pragma unroll
            for (int jp = 0; jp < 4; jp++) {
                uint32_t vhf[2][4];
#pragma unroll
                for (int u = 0; u < 2; u++) {
                    const int j4 = 2 * jp + u;
                    const uint32_t vo = (j4 * 16 + brow) * 144 + kp * 32 + boff;
                    ldsm_x4(vhf[u], vb + vo);
                }
#pragma unroll
                for (int u = 0; u < 2; u++) {
                    const int j4 = 2 * jp + u;
                    mma16816(O[2 * j4],     Ph[kp], vhf[u]);
                    mma16816(O[2 * j4 + 1], Ph[kp], vhf[u] + 2);
                }
#pragma unroll
                for (int u = 0; u < 2; u++) {
                    const int j4 = 2 * jp + u;
                    mma16816(O[2 * j4],     Pl[kp], vhf[u]);
                    mma16816(O[2 * j4 + 1], Pl[kp], vhf[u] + 2);
                }
            }
        }
        __syncthreads();
    }

    const float inva = 1.0f / la, invb = 1.0f / lb;
    const size_t rowa = bT + q0 + wid * 16 + g;
    const size_t rowb = rowa + 8;
#pragma unroll
    for (int j2 = 0; j2 < 16; j2++) {
        const int col = hoff + j2 * 8 + tq * 2;
        uint32_t h0, l0, h1, l1;
        pack_hl(O[j2][0] * inva, O[j2][1] * inva, h0, l0);
        pack_hl(O[j2][2] * invb, O[j2][3] * invb, h1, l1);
        *(uint32_t*)(yh + rowa * N_EMBD + col) = h0;
        *(uint32_t*)(yl + rowa * N_EMBD + col) = l0;
        *(uint32_t*)(yh + rowb * N_EMBD + col) = h1;
        *(uint32_t*)(yl + rowb * N_EMBD + col) = l1;
    }
}

// ---------------------------------------------------------------------------
// Launch
// ---------------------------------------------------------------------------
extern "C" void kernel_launch(void* const* d_in, const int* in_sizes, int n_in,
                              void* d_out, int out_size)
{
    const float* x      = (const float*)d_in[0];
    const float* w_attn = (const float*)d_in[1];
    const float* w_proj = (const float*)d_in[2];
    float* out = (float*)d_out;

    __half *Ah, *Al, *Wa, *Wp, *Qh, *Ql, *Kb, *Vh, *Vt;
    cudaGetSymbolAddress((void**)&Ah, g_Ah);
    cudaGetSymbolAddress((void**)&Al, g_Al);
    cudaGetSymbolAddress((void**)&Wa, g_Wa);
    cudaGetSymbolAddress((void**)&Wp, g_Wp);
    cudaGetSymbolAddress((void**)&Qh, g_Qh);
    cudaGetSymbolAddress((void**)&Ql, g_Ql);
    cudaGetSymbolAddress((void**)&Kb, g_K);
    cudaGetSymbolAddress((void**)&Vh, g_Vh);
    cudaGetSymbolAddress((void**)&Vt, g_Vt);

    cudaFuncSetAttribute(gemm_qkv_kernel,
                         cudaFuncAttributeMaxDynamicSharedMemorySize, QKV_SMEM);
    cudaFuncSetAttribute(gemm_proj_kernel,
                         cudaFuncAttributeMaxDynamicSharedMemorySize, PROJ_SMEM);
    cudaFuncSetAttribute(flash_mma_kernel,
                         cudaFuncAttributeMaxDynamicSharedMemorySize, FA_SMEM);

    const int n4 = MROWS * N_EMBD / 4;

    rope_table_kernel<<<(TT * 64 + 255) / 256, 256>>>();

    conv_rm_kernel<<<(n4 + 255) / 256, 256>>>(x, Ah, Al, n4);
    conv_tr_kernel<<<dim3(QKV_N / 32, N_EMBD / 32), dim3(32, 8)>>>(
        w_attn, Wa, N_EMBD, QKV_N);
    conv_tr_kernel<<<dim3(N_EMBD / 32, N_EMBD / 32), dim3(32, 8)>>>(
        w_proj, Wp, N_EMBD, N_EMBD);

    // QKV projection (BN=192 -> 1024 CTAs, 98.8% wave efficiency)
    gemm_qkv_kernel<<<dim3(QKV_N / BN6, MROWS / BM), 256, QKV_SMEM>>>(
        Ah, Al, Wa, Qh, Ql, Kb, Vh);

    conv_vth_kernel<<<dim3(TT / 32, HD / 32, BB * NH), dim3(32, 8)>>>(Vh, Vt);

    flash_mma_kernel<<<dim3(TT / 128, NH, BB), 256, FA_SMEM>>>(
        Qh, Ql, Kb, Vt, Ah, Al);

    gemm_proj_kernel<<<dim3(N_EMBD / BN4, MROWS / BM), 256, PROJ_SMEM>>>(
        Ah, Al, Wp, out, MROWS, N_EMBD, N_EMBD);
}

// round 14
// speedup vs baseline: 1.1867x; 1.1196x over previous
#include <cuda_runtime.h>
#include <cuda_fp16.h>
#include <stdint.h>
#include <math.h>

// ---------------------------------------------------------------------------
// Problem constants
// ---------------------------------------------------------------------------
#define N_EMBD 2048
#define NH     16
#define HD     128
#define TT     2048
#define BB     2
#define MROWS  (BB * TT)
#define QKV_N  (3 * N_EMBD)

// ---------------------------------------------------------------------------
// Scratch
// ---------------------------------------------------------------------------
__device__ float g_cos[TT * (HD / 2)];
__device__ float g_sin[TT * (HD / 2)];
__device__ __half g_Ah[(size_t)MROWS * N_EMBD];   // x-hi, later y-hi
__device__ __half g_Al[(size_t)MROWS * N_EMBD];   // x-lo, later y-lo
__device__ __half g_Wa[(size_t)QKV_N * N_EMBD];
__device__ __half g_Wp[(size_t)N_EMBD * N_EMBD];
__device__ __half g_Q [(size_t)MROWS * N_EMBD];   // roped q (single fp16)
__device__ __half g_K [(size_t)MROWS * N_EMBD];   // roped k (single fp16)
__device__ __half g_Vh[(size_t)MROWS * N_EMBD];   // v row-major
__device__ __half g_Vt[(size_t)MROWS * N_EMBD];   // V^T per head [bh][d][t]

// ---------------------------------------------------------------------------
// Helpers
// ---------------------------------------------------------------------------
__device__ __forceinline__ uint32_t smem_u32(const void* p) {
    uint32_t a;
    asm("{ .reg .u64 t; cvta.to.shared.u64 t, %1; cvt.u32.u64 %0, t; }"
        : "=r"(a) : "l"(p));
    return a;
}

__device__ __forceinline__ void ldsm_x4(uint32_t* r, uint32_t addr) {
    asm volatile("ldmatrix.sync.aligned.m8n8.x4.shared.b16 {%0,%1,%2,%3}, [%4];"
                 : "=r"(r[0]), "=r"(r[1]), "=r"(r[2]), "=r"(r[3]) : "r"(addr));
}

__device__ __forceinline__ void mma16816(float* c, const uint32_t* a,
                                         const uint32_t* b) {
    asm volatile(
        "mma.sync.aligned.m16n8k16.row.col.f32.f16.f16.f32 "
        "{%0,%1,%2,%3}, {%4,%5,%6,%7}, {%8,%9}, {%0,%1,%2,%3};"
        : "+f"(c[0]), "+f"(c[1]), "+f"(c[2]), "+f"(c[3])
        : "r"(a[0]), "r"(a[1]), "r"(a[2]), "r"(a[3]), "r"(b[0]), "r"(b[1]));
}

#define CP_ASYNC16(dst, src) \
    asm volatile("cp.async.cg.shared.global [%0], [%1], 16;" \
                 :: "r"(dst), "l"(src) : "memory")
#define CP_COMMIT() asm volatile("cp.async.commit_group;" ::: "memory")
#define CP_WAIT1()  asm volatile("cp.async.wait_group 1;" ::: "memory")

__device__ __forceinline__ void pack_hl(float x, float y, uint32_t& h, uint32_t& l) {
    __half2 hh = __floats2half2_rn(x, y);
    float rx = x - __half2float(__low2half(hh));
    float ry = y - __half2float(__high2half(hh));
    __half2 ll = __floats2half2_rn(rx, ry);
    h = *(uint32_t*)&hh;
    l = *(uint32_t*)&ll;
}

__device__ __forceinline__ uint32_t pack_h(float x, float y) {
    __half2 hh = __floats2half2_rn(x, y);
    return *(uint32_t*)&hh;
}

// ---------------------------------------------------------------------------
// Convert kernels
// ---------------------------------------------------------------------------
__global__ void conv_rm_kernel(const float* __restrict__ in,
                               __half* __restrict__ oh,
                               __half* __restrict__ ol, int n4) {
    int idx = blockIdx.x * blockDim.x + threadIdx.x;
    if (idx >= n4) return;
    float4 v = ((const float4*)in)[idx];
    __half2 h01 = __floats2half2_rn(v.x, v.y);
    __half2 h23 = __floats2half2_rn(v.z, v.w);
    __half2 l01 = __floats2half2_rn(v.x - __half2float(__low2half(h01)),
                                    v.y - __half2float(__high2half(h01)));
    __half2 l23 = __floats2half2_rn(v.z - __half2float(__low2half(h23)),
                                    v.w - __half2float(__high2half(h23)));
    ((__half2*)oh)[idx * 2]     = h01;
    ((__half2*)oh)[idx * 2 + 1] = h23;
    ((__half2*)ol)[idx * 2]     = l01;
    ((__half2*)ol)[idx * 2 + 1] = l23;
}

__global__ void conv_tr_kernel(const float* __restrict__ B,
                               __half* __restrict__ bt, int K, int N) {
    __shared__ float tile[32][33];
    int n0 = blockIdx.x * 32, k0 = blockIdx.y * 32;
    int tx = threadIdx.x, ty = threadIdx.y;
#pragma unroll
    for (int i = 0; i < 4; i++)
        tile[ty + i * 8][tx] = B[(size_t)(k0 + ty + i * 8) * N + n0 + tx];
    __syncthreads();
#pragma unroll
    for (int i = 0; i < 4; i++) {
        int n = ty + i * 8;
        bt[(size_t)(n0 + n) * K + k0 + tx] = __float2half_rn(tile[tx][n]);
    }
}

__global__ void conv_vth_kernel(const __half* __restrict__ vh,
                                __half* __restrict__ vt) {
    __shared__ __half tile[32][34];
    int bh = blockIdx.z;
    int b = bh >> 4, h = bh & 15;
    int t0 = blockIdx.x * 32, d0 = blockIdx.y * 32;
    int tx = threadIdx.x, ty = threadIdx.y;
#pragma unroll
    for (int i = 0; i < 4; i++)
        tile[ty + i * 8][tx] =
            vh[(size_t)(b * TT + t0 + ty + i * 8) * N_EMBD + h * HD + d0 + tx];
    __syncthreads();
#pragma unroll
    for (int i = 0; i < 4; i++) {
        int d = ty + i * 8;
        vt[(size_t)(bh * HD + d0 + d) * TT + t0 + tx] = tile[tx][d];
    }
}

__global__ void rope_table_kernel() {
    int idx = blockIdx.x * blockDim.x + threadIdx.x;
    if (idx >= TT * 64) return;
    int t = idx >> 6;
    int i = idx & 63;
    double theta = pow(10000.0, -(double)i / 64.0);
    double ang = (double)t * theta;
    g_cos[idx] = (float)cos(ang);
    g_sin[idx] = (float)sin(ang);
}

// ---------------------------------------------------------------------------
// GEMM config
// ---------------------------------------------------------------------------
#define BM 128
#define BK 32
#define PADB 80
#define A_BYTES (128 * PADB)

// QKV: BN=192 -> 1024 CTAs -> 98.8% wave efficiency
#define BN6 192
#define B6_BYTES (192 * PADB)
#define STG6 (2 * A_BYTES + B6_BYTES)            // 35840
#define QKV_SMEM (2 * STG6)                      // 71680

// Proj: BN=256
#define BN4 256
#define B4_BYTES (256 * PADB)
#define STG4 (2 * A_BYTES + B4_BYTES)            // 40960
#define PROJ_SMEM (2 * STG4)                     // 81920

// ---------------------------------------------------------------------------
// QKV GEMM (BN=192, fp32-acc 2-term) with fused RoPE/convert epilogue.
// q -> RoPE + single fp16 Q; k -> RoPE + single fp16 K; v -> single fp16 Vh.
// ---------------------------------------------------------------------------
__global__ __launch_bounds__(256, 1) void gemm_qkv_kernel(
    const __half* __restrict__ Ah, const __half* __restrict__ Al,
    const __half* __restrict__ B,
    __half* __restrict__ Q, __half* __restrict__ Kb, __half* __restrict__ Vh)
{
    const int K = N_EMBD;
    extern __shared__ char smc[];
    const uint32_t sbase = smem_u32(smc);
    const int tid = threadIdx.x;
    const int lane = tid & 31;
    const int wid = tid >> 5;
    const int wm = wid & 1;
    const int wn = wid >> 1;
    const int mBase = blockIdx.y * BM;
    const int nBase = blockIdx.x * BN6;
    const int nch = K / BK;

    const int ldRow = tid >> 2;
    const int ldCh  = tid & 3;

    float acc[4][6][4];
#pragma unroll
    for (int i = 0; i < 4; i++)
#pragma unroll
        for (int j = 0; j < 6; j++)
#pragma unroll
            for (int r = 0; r < 4; r++) acc[i][j][r] = 0.0f;

    auto issue_stage = [&](int c, int buf) {
        const uint32_t st = sbase + buf * STG6;
        const int kOff = c * BK;
#pragma unroll
        for (int i = 0; i < 2; i++) {
            const int row = i * 64 + ldRow;
            const uint32_t so = row * PADB + ldCh * 16;
            CP_ASYNC16(st + so,
                       Ah + (size_t)(mBase + row) * K + kOff + ldCh * 8);
            CP_ASYNC16(st + A_BYTES + so,
                       Al + (size_t)(mBase + row) * K + kOff + ldCh * 8);
        }
#pragma unroll
        for (int i = 0; i < 3; i++) {
            const int row = i * 64 + ldRow;
            const uint32_t so = row * PADB + ldCh * 16;
            CP_ASYNC16(st + 2 * A_BYTES + so,
                       B + (size_t)(nBase + row) * K + kOff + ldCh * 8);
        }
    };

    issue_stage(0, 0);
    CP_COMMIT();

    const int arow = (lane & 7) + ((lane >> 3) & 1) * 8;
    const int akc8 = (lane >> 4) * 8;
    const int brow = (lane & 7) + ((lane >> 4) & 1) * 8;
    const int bkc8 = ((lane >> 3) & 1) * 8;

    for (int c = 0; c < nch; c++) {
        const int buf = c & 1;
        if (c + 1 < nch) issue_stage(c + 1, (c + 1) & 1);
        CP_COMMIT();
        CP_WAIT1();
        __syncthreads();

        const uint32_t st = sbase + buf * STG6;
        const uint32_t ahB = st;
        const uint32_t alB = st + A_BYTES;
        const uint32_t bB  = st + 2 * A_BYTES;

#pragma unroll
        for (int s = 0; s < 2; s++) {
            const int kofs = s * 16;
            uint32_t ah[4][4], al[4][4];
#pragma unroll
            for (int fm = 0; fm < 4; fm++) {
                const uint32_t off =
                    (uint32_t)((wm * 64 + fm * 16 + arow) * PADB +
                               (kofs + akc8) * 2);
                ldsm_x4(ah[fm], ahB + off);
                ldsm_x4(al[fm], alB + off);
            }
#pragma unroll
            for (int bi = 0; bi < 3; bi++) {
                uint32_t bf[4];
                const uint32_t off =
                    (uint32_t)((wn * 48 + bi * 16 + brow) * PADB +
                               (kofs + bkc8) * 2);
                ldsm_x4(bf, bB + off);
#pragma unroll
                for (int fm = 0; fm < 4; fm++) {
                    mma16816(acc[fm][2 * bi],     ah[fm], bf);
                    mma16816(acc[fm][2 * bi + 1], ah[fm], bf + 2);
                }
#pragma unroll
                for (int fm = 0; fm < 4; fm++) {
                    mma16816(acc[fm][2 * bi],     al[fm], bf);
                    mma16816(acc[fm][2 * bi + 1], al[fm], bf + 2);
                }
            }
        }
        __syncthreads();
    }

    // ---- fused epilogue ----
    const int r0 = lane >> 2;
    const int c0 = (lane & 3) * 2;
#pragma unroll
    for (int fm = 0; fm < 4; fm++) {
        const int row = mBase + wm * 64 + fm * 16 + r0;
        const int t0 = row & (TT - 1);
        const int t1 = (row + 8) & (TT - 1);
#pragma unroll
        for (int fn = 0; fn < 6; fn++) {
            const float v0 = acc[fm][fn][0], v1 = acc[fm][fn][1];
            const float v2 = acc[fm][fn][2], v3 = acc[fm][fn][3];
            const int col = nBase + wn * 48 + fn * 8 + c0;
            const int sec = col >> 11;
            const int cloc = col & (N_EMBD - 1);
            if (sec < 2) {
                const int i0 = (cloc & 127) >> 1;
                float cA = g_cos[t0 * 64 + i0], sA = g_sin[t0 * 64 + i0];
                float cB = g_cos[t1 * 64 + i0], sB = g_sin[t1 * 64 + i0];
                float r00 = v0 * cA - v1 * sA, r01 = v1 * cA + v0 * sA;
                float r10 = v2 * cB - v3 * sB, r11 = v3 * cB + v2 * sB;
                __half* dst = (sec == 0) ? Q : Kb;
                *(uint32_t*)(dst + (size_t)row * N_EMBD + cloc) =
                    pack_h(r00, r01);
                *(uint32_t*)(dst + (size_t)(row + 8) * N_EMBD + cloc) =
                    pack_h(r10, r11);
            } else {
                *(uint32_t*)(Vh + (size_t)row * N_EMBD + cloc) =
                    pack_h(v0, v1);
                *(uint32_t*)(Vh + (size_t)(row + 8) * N_EMBD + cloc) =
                    pack_h(v2, v3);
            }
        }
    }
}

// ---------------------------------------------------------------------------
// Proj GEMM (BN=256): fp32 out (unchanged, 2-term A split)
// ---------------------------------------------------------------------------
__global__ __launch_bounds__(256, 1) void gemm_proj_kernel(
    const __half* __restrict__ Ah, const __half* __restrict__ Al,
    const __half* __restrict__ B,
    float* __restrict__ C, int M, int N, int K)
{
    extern __shared__ char smc[];
    const uint32_t sbase = smem_u32(smc);
    const int tid = threadIdx.x;
    const int lane = tid & 31;
    const int wid = tid >> 5;
    const int wm = wid & 1;
    const int wn = wid >> 1;
    const int mBase = blockIdx.y * BM;
    const int nBase = blockIdx.x * BN4;
    const int nch = K / BK;

    const int ldRow = tid >> 2;
    const int ldCh  = tid & 3;

    float acc[4][8][4];
#pragma unroll
    for (int i = 0; i < 4; i++)
#pragma unroll
        for (int j = 0; j < 8; j++)
#pragma unroll
            for (int r = 0; r < 4; r++) acc[i][j][r] = 0.0f;

    auto issue_stage = [&](int c, int buf) {
        const uint32_t st = sbase + buf * STG4;
        const int kOff = c * BK;
#pragma unroll
        for (int i = 0; i < 2; i++) {
            const int row = i * 64 + ldRow;
            const uint32_t so = row * PADB + ldCh * 16;
            CP_ASYNC16(st + so,
                       Ah + (size_t)(mBase + row) * K + kOff + ldCh * 8);
            CP_ASYNC16(st + A_BYTES + so,
                       Al + (size_t)(mBase + row) * K + kOff + ldCh * 8);
        }
#pragma unroll
        for (int i = 0; i < 4; i++) {
            const int row = i * 64 + ldRow;
            const uint32_t so = row * PADB + ldCh * 16;
            CP_ASYNC16(st + 2 * A_BYTES + so,
                       B + (size_t)(nBase + row) * K + kOff + ldCh * 8);
        }
    };

    issue_stage(0, 0);
    CP_COMMIT();

    const int arow = (lane & 7) + ((lane >> 3) & 1) * 8;
    const int akc8 = (lane >> 4) * 8;
    const int brow = (lane & 7) + ((lane >> 4) & 1) * 8;
    const int bkc8 = ((lane >> 3) & 1) * 8;

    for (int c = 0; c < nch; c++) {
        const int buf = c & 1;
        if (c + 1 < nch) issue_stage(c + 1, (c + 1) & 1);
        CP_COMMIT();
        CP_WAIT1();
        __syncthreads();

        const uint32_t st = sbase + buf * STG4;
        const uint32_t ahB = st;
        const uint32_t alB = st + A_BYTES;
        const uint32_t bB  = st + 2 * A_BYTES;

#pragma unroll
        for (int s = 0; s < 2; s++) {
            const int kofs = s * 16;
            uint32_t ah[4][4], al[4][4];
#pragma unroll
            for (int fm = 0; fm < 4; fm++) {
                const uint32_t off =
                    (uint32_t)((wm * 64 + fm * 16 + arow) * PADB +
                               (kofs + akc8) * 2);
                ldsm_x4(ah[fm], ahB + off);
                ldsm_x4(al[fm], alB + off);
            }
#pragma unroll
            for (int bi = 0; bi < 4; bi++) {
                uint32_t bf[4];
                const uint32_t off =
                    (uint32_t)((wn * 64 + bi * 16 + brow) * PADB +
                               (kofs + bkc8) * 2);
                ldsm_x4(bf, bB + off);
#pragma unroll
                for (int fm = 0; fm < 4; fm++) {
                    mma16816(acc[fm][2 * bi],     ah[fm], bf);
                    mma16816(acc[fm][2 * bi + 1], ah[fm], bf + 2);
                }
#pragma unroll
                for (int fm = 0; fm < 4; fm++) {
                    mma16816(acc[fm][2 * bi],     al[fm], bf);
                    mma16816(acc[fm][2 * bi + 1], al[fm], bf + 2);
                }
            }
        }
        __syncthreads();
    }

    const int r0 = lane >> 2;
    const int c0 = (lane & 3) * 2;
#pragma unroll
    for (int fm = 0; fm < 4; fm++) {
#pragma unroll
        for (int fn = 0; fn < 8; fn++) {
            const size_t row = (size_t)(mBase + wm * 64 + fm * 16 + r0);
            const int col = nBase + wn * 64 + fn * 8 + c0;
            *(float2*)(C + row * N + col) =
                make_float2(acc[fm][fn][0], acc[fm][fn][1]);
            *(float2*)(C + (row + 8) * N + col) =
                make_float2(acc[fm][fn][2], acc[fm][fn][3]);
        }
    }
}

// ---------------------------------------------------------------------------
// Flash attention: SINGLE fp16 Q, K, P, V (half the MMAs of R12).
// Epilogue writes split fp16 O into Ah/Al for the 2-term proj GEMM.
// ---------------------------------------------------------------------------
#define FQ_BYTES   (128 * 272)
#define FK_BYTES   (64 * 272)
#define FV_BYTES   (128 * 144)
#define FSTAGE     (FK_BYTES + FV_BYTES)
#define FA_SMEM    (FQ_BYTES + 2 * FSTAGE)       // 106496

__global__ __launch_bounds__(256, 1) void flash_mma_kernel(
    const __half* __restrict__ q, const __half* __restrict__ kh,
    const __half* __restrict__ vt,
    __half* __restrict__ yh, __half* __restrict__ yl)
{
    extern __shared__ char smc[];
    const uint32_t sbase = smem_u32(smc);
    const int tid = threadIdx.x;
    const int lane = tid & 31;
    const int wid = tid >> 5;
    const int b = blockIdx.z, h = blockIdx.y;
    const int bh = b * NH + h;
    const int q0 = blockIdx.x * 128;
    const size_t bT = (size_t)b * TT;
    const int hoff = h * HD;

    {
#pragma unroll
        for (int i = 0; i < 8; i++) {
            int cid = i * 256 + tid;
            int row = cid >> 4, ch = cid & 15;
            CP_ASYNC16(sbase + row * 272 + ch * 16,
                       q + (bT + q0 + row) * N_EMBD + hoff + ch * 8);
        }
        CP_COMMIT();
    }

    auto issue_stage = [&](int it, int buf) {
        const uint32_t st = sbase + FQ_BYTES + buf * FSTAGE;
        const int n0 = it * 64;
#pragma unroll
        for (int i = 0; i < 4; i++) {
            int cid = i * 256 + tid;
            int row = cid >> 4, ch = cid & 15;
            CP_ASYNC16(st + row * 272 + ch * 16,
                       kh + (bT + n0 + row) * N_EMBD + hoff + ch * 8);
        }
#pragma unroll
        for (int i = 0; i < 4; i++) {
            int cid = i * 256 + tid;
            int row = cid >> 3, ch = cid & 7;
            CP_ASYNC16(st + FK_BYTES + row * 144 + ch * 16,
                       vt + (size_t)(bh * HD + row) * TT + n0 + ch * 8);
        }
    };

    issue_stage(0, 0);
    CP_COMMIT();

    const int arow = (lane & 7) + ((lane >> 3) & 1) * 8;
    const int aoff = (lane >> 4) * 16;
    const int brow = (lane & 7) + ((lane >> 4) & 1) * 8;
    const int boff = ((lane >> 3) & 1) * 16;
    const int g = lane >> 2;
    const int tq = lane & 3;

    float O[16][4];
#pragma unroll
    for (int i = 0; i < 16; i++)
#pragma unroll
        for (int r = 0; r < 4; r++) O[i][r] = 0.0f;
    float ma = -INFINITY, mb = -INFINITY, la = 0.0f, lb = 0.0f;
    const float sc = 0.08838834764831845f;

    const int niter = TT / 64;
    for (int c = 0; c < niter; c++) {
        const int buf = c & 1;
        if (c + 1 < niter) issue_stage(c + 1, (c + 1) & 1);
        CP_COMMIT();
        CP_WAIT1();
        __syncthreads();

        const uint32_t kb = sbase + FQ_BYTES + buf * FSTAGE;

        // ---- S = Q @ K^T (single-term) ----
        float s[8][4];
#pragma unroll
        for (int j = 0; j < 8; j++)
#pragma unroll
            for (int r = 0; r < 4; r++) s[j][r] = 0.0f;

#pragma unroll
        for (int kk = 0; kk < 8; kk++) {
            uint32_t qf[4];
            const uint32_t qo = (wid * 16 + arow) * 272 + kk * 32 + aoff;
            ldsm_x4(qf, sbase + qo);
#pragma unroll
            for (int bp = 0; bp < 2; bp++) {
                uint32_t khf[2][4];
#pragma unroll
                for (int u = 0; u < 2; u++) {
                    const int bi = 2 * bp + u;
                    const uint32_t ko = (bi * 16 + brow) * 272 + kk * 32 + boff;
                    ldsm_x4(khf[u], kb + ko);
                }
#pragma unroll
                for (int u = 0; u < 2; u++) {
                    const int bi = 2 * bp + u;
                    mma16816(s[2 * bi],     qf, khf[u]);
                    mma16816(s[2 * bi + 1], qf, khf[u] + 2);
                }
            }
        }

        // ---- online softmax ----
        float mxa = -INFINITY, mxb = -INFINITY;
#pragma unroll
        for (int j = 0; j < 8; j++) {
            s[j][0] *= sc; s[j][1] *= sc; s[j][2] *= sc; s[j][3] *= sc;
            mxa = fmaxf(mxa, fmaxf(s[j][0], s[j][1]));
            mxb = fmaxf(mxb, fmaxf(s[j][2], s[j][3]));
        }
        mxa = fmaxf(mxa, __shfl_xor_sync(0xffffffffu, mxa, 1));
        mxa = fmaxf(mxa, __shfl_xor_sync(0xffffffffu, mxa, 2));
        mxb = fmaxf(mxb, __shfl_xor_sync(0xffffffffu, mxb, 1));
        mxb = fmaxf(mxb, __shfl_xor_sync(0xffffffffu, mxb, 2));
        float mna = fmaxf(ma, mxa), mnb = fmaxf(mb, mxb);
        float alpha = __expf(ma - mna), beta = __expf(mb - mnb);
        ma = mna; mb = mnb;
        float sua = 0.0f, sub = 0.0f;
#pragma unroll
        for (int j = 0; j < 8; j++) {
            s[j][0] = __expf(s[j][0] - mna);
            s[j][1] = __expf(s[j][1] - mna);
            s[j][2] = __expf(s[j][2] - mnb);
            s[j][3] = __expf(s[j][3] - mnb);
            sua += s[j][0] + s[j][1];
            sub += s[j][2] + s[j][3];
        }
        sua += __shfl_xor_sync(0xffffffffu, sua, 1);
        sua += __shfl_xor_sync(0xffffffffu, sua, 2);
        sub += __shfl_xor_sync(0xffffffffu, sub, 1);
        sub += __shfl_xor_sync(0xffffffffu, sub, 2);
        la = la * alpha + sua;
        lb = lb * beta + sub;
#pragma unroll
        for (int j2 = 0; j2 < 16; j2++) {
            O[j2][0] *= alpha; O[j2][1] *= alpha;
            O[j2][2] *= beta;  O[j2][3] *= beta;
        }

        // ---- P -> single fp16 A-fragments ----
        uint32_t Ph[4][4];
#pragma unroll
        for (int kp = 0; kp < 4; kp++) {
            Ph[kp][0] = pack_h(s[2 * kp][0],     s[2 * kp][1]);
            Ph[kp][1] = pack_h(s[2 * kp][2],     s[2 * kp][3]);
            Ph[kp][2] = pack_h(s[2 * kp + 1][0], s[2 * kp + 1][1]);
            Ph[kp][3] = pack_h(s[2 * kp + 1][2], s[2 * kp + 1][3]);
        }

        // ---- O += P @ V (single-term) ----
        const uint32_t vb = kb + FK_BYTES;
#pragma unroll
        for (int kp = 0; kp < 4; kp++) {
#pragma unroll
            for (int jp = 0; jp < 4; jp++) {
                uint32_t vhf[2][4];
#pragma unroll
                for (int u = 0; u < 2; u++) {
                    const int j4 = 2 * jp + u;
                    const uint32_t vo = (j4 * 16 + brow) * 144 + kp * 32 + boff;
                    ldsm_x4(vhf[u], vb + vo);
                }
#pragma unroll
                for (int u = 0; u < 2; u++) {
                    const int j4 = 2 * jp + u;
                    mma16816(O[2 * j4],     Ph[kp], vhf[u]);
                    mma16816(O[2 * j4 + 1], Ph[kp], vhf[u] + 2);
                }
            }
        }
        __syncthreads();
    }

    // ---- epilogue: normalize + split fp16 hi/lo into Ah/Al ----
    const float inva = 1.0f / la, invb = 1.0f / lb;
    const size_t rowa = bT + q0 + wid * 16 + g;
    const size_t rowb = rowa + 8;
#pragma unroll
    for (int j2 = 0; j2 < 16; j2++) {
        const int col = hoff + j2 * 8 + tq * 2;
        uint32_t h0, l0, h1, l1;
        pack_hl(O[j2][0] * inva, O[j2][1] * inva, h0, l0);
        pack_hl(O[j2][2] * invb, O[j2][3] * invb, h1, l1);
        *(uint32_t*)(yh + rowa * N_EMBD + col) = h0;
        *(uint32_t*)(yl + rowa * N_EMBD + col) = l0;
        *(uint32_t*)(yh + rowb * N_EMBD + col) = h1;
        *(uint32_t*)(yl + rowb * N_EMBD + col) = l1;
    }
}

// ---------------------------------------------------------------------------
// Launch
// ---------------------------------------------------------------------------
extern "C" void kernel_launch(void* const* d_in, const int* in_sizes, int n_in,
                              void* d_out, int out_size)
{
    const float* x      = (const float*)d_in[0];
    const float* w_attn = (const float*)d_in[1];
    const float* w_proj = (const float*)d_in[2];
    float* out = (float*)d_out;

    __half *Ah, *Al, *Wa, *Wp, *Q, *Kb, *Vh, *Vt;
    cudaGetSymbolAddress((void**)&Ah, g_Ah);
    cudaGetSymbolAddress((void**)&Al, g_Al);
    cudaGetSymbolAddress((void**)&Wa, g_Wa);
    cudaGetSymbolAddress((void**)&Wp, g_Wp);
    cudaGetSymbolAddress((void**)&Q, g_Q);
    cudaGetSymbolAddress((void**)&Kb, g_K);
    cudaGetSymbolAddress((void**)&Vh, g_Vh);
    cudaGetSymbolAddress((void**)&Vt, g_Vt);

    cudaFuncSetAttribute(gemm_qkv_kernel,
                         cudaFuncAttributeMaxDynamicSharedMemorySize, QKV_SMEM);
    cudaFuncSetAttribute(gemm_proj_kernel,
                         cudaFuncAttributeMaxDynamicSharedMemorySize, PROJ_SMEM);
    cudaFuncSetAttribute(flash_mma_kernel,
                         cudaFuncAttributeMaxDynamicSharedMemorySize, FA_SMEM);

    const int n4 = MROWS * N_EMBD / 4;

    rope_table_kernel<<<(TT * 64 + 255) / 256, 256>>>();

    conv_rm_kernel<<<(n4 + 255) / 256, 256>>>(x, Ah, Al, n4);
    conv_tr_kernel<<<dim3(QKV_N / 32, N_EMBD / 32), dim3(32, 8)>>>(
        w_attn, Wa, N_EMBD, QKV_N);
    conv_tr_kernel<<<dim3(N_EMBD / 32, N_EMBD / 32), dim3(32, 8)>>>(
        w_proj, Wp, N_EMBD, N_EMBD);

    // QKV projection (fused RoPE + single-fp16 q/k/v epilogue)
    gemm_qkv_kernel<<<dim3(QKV_N / BN6, MROWS / BM), 256, QKV_SMEM>>>(
        Ah, Al, Wa, Q, Kb, Vh);

    conv_vth_kernel<<<dim3(TT / 32, HD / 32, BB * NH), dim3(32, 8)>>>(Vh, Vt);

    // Flash attention (single-fp16 operands, half the MMAs)
    flash_mma_kernel<<<dim3(TT / 128, NH, BB), 256, FA_SMEM>>>(
        Q, Kb, Vt, Ah, Al);

    gemm_proj_kernel<<<dim3(N_EMBD / BN4, MROWS / BM), 256, PROJ_SMEM>>>(
        Ah, Al, Wp, out, MROWS, N_EMBD, N_EMBD);
}

// round 15
// speedup vs baseline: 1.5870x; 1.3373x over previous
#include <cuda_runtime.h>
#include <cuda_fp16.h>
#include <stdint.h>
#include <math.h>

// ---------------------------------------------------------------------------
// Problem constants
// ---------------------------------------------------------------------------
#define N_EMBD 2048
#define NH     16
#define HD     128
#define TT     2048
#define BB     2
#define MROWS  (BB * TT)
#define QKV_N  (3 * N_EMBD)

// ---------------------------------------------------------------------------
// Scratch
// ---------------------------------------------------------------------------
__device__ float g_cos[TT * (HD / 2)];
__device__ float g_sin[TT * (HD / 2)];
__device__ __half g_A [(size_t)MROWS * N_EMBD];   // x (single), later y (single)
__device__ __half g_Wa[(size_t)QKV_N * N_EMBD];
__device__ __half g_Wp[(size_t)N_EMBD * N_EMBD];
__device__ __half g_Q [(size_t)MROWS * N_EMBD];   // roped q
__device__ __half g_K [(size_t)MROWS * N_EMBD];   // roped k
__device__ __half g_Vh[(size_t)MROWS * N_EMBD];   // v row-major
__device__ __half g_Vt[(size_t)MROWS * N_EMBD];   // V^T per head [bh][d][t]

// ---------------------------------------------------------------------------
// Helpers
// ---------------------------------------------------------------------------
__device__ __forceinline__ uint32_t smem_u32(const void* p) {
    uint32_t a;
    asm("{ .reg .u64 t; cvta.to.shared.u64 t, %1; cvt.u32.u64 %0, t; }"
        : "=r"(a) : "l"(p));
    return a;
}

__device__ __forceinline__ void ldsm_x4(uint32_t* r, uint32_t addr) {
    asm volatile("ldmatrix.sync.aligned.m8n8.x4.shared.b16 {%0,%1,%2,%3}, [%4];"
                 : "=r"(r[0]), "=r"(r[1]), "=r"(r[2]), "=r"(r[3]) : "r"(addr));
}

__device__ __forceinline__ void mma16816(float* c, const uint32_t* a,
                                         const uint32_t* b) {
    asm volatile(
        "mma.sync.aligned.m16n8k16.row.col.f32.f16.f16.f32 "
        "{%0,%1,%2,%3}, {%4,%5,%6,%7}, {%8,%9}, {%0,%1,%2,%3};"
        : "+f"(c[0]), "+f"(c[1]), "+f"(c[2]), "+f"(c[3])
        : "r"(a[0]), "r"(a[1]), "r"(a[2]), "r"(a[3]), "r"(b[0]), "r"(b[1]));
}

#define CP_ASYNC16(dst, src) \
    asm volatile("cp.async.cg.shared.global [%0], [%1], 16;" \
                 :: "r"(dst), "l"(src) : "memory")
#define CP_COMMIT() asm volatile("cp.async.commit_group;" ::: "memory")
#define CP_WAIT1()  asm volatile("cp.async.wait_group 1;" ::: "memory")

__device__ __forceinline__ uint32_t pack_h(float x, float y) {
    __half2 hh = __floats2half2_rn(x, y);
    return *(uint32_t*)&hh;
}

// ---------------------------------------------------------------------------
// Convert kernels
// ---------------------------------------------------------------------------
// fp32 row-major -> single fp16 (same layout)
__global__ void conv_single_kernel(const float* __restrict__ in,
                                   __half* __restrict__ o, int n4) {
    int idx = blockIdx.x * blockDim.x + threadIdx.x;
    if (idx >= n4) return;
    float4 v = ((const float4*)in)[idx];
    ((__half2*)o)[idx * 2]     = __floats2half2_rn(v.x, v.y);
    ((__half2*)o)[idx * 2 + 1] = __floats2half2_rn(v.z, v.w);
}

__global__ void conv_tr_kernel(const float* __restrict__ B,
                               __half* __restrict__ bt, int K, int N) {
    __shared__ float tile[32][33];
    int n0 = blockIdx.x * 32, k0 = blockIdx.y * 32;
    int tx = threadIdx.x, ty = threadIdx.y;
#pragma unroll
    for (int i = 0; i < 4; i++)
        tile[ty + i * 8][tx] = B[(size_t)(k0 + ty + i * 8) * N + n0 + tx];
    __syncthreads();
#pragma unroll
    for (int i = 0; i < 4; i++) {
        int n = ty + i * 8;
        bt[(size_t)(n0 + n) * K + k0 + tx] = __float2half_rn(tile[tx][n]);
    }
}

__global__ void conv_vth_kernel(const __half* __restrict__ vh,
                                __half* __restrict__ vt) {
    __shared__ __half tile[32][34];
    int bh = blockIdx.z;
    int b = bh >> 4, h = bh & 15;
    int t0 = blockIdx.x * 32, d0 = blockIdx.y * 32;
    int tx = threadIdx.x, ty = threadIdx.y;
#pragma unroll
    for (int i = 0; i < 4; i++)
        tile[ty + i * 8][tx] =
            vh[(size_t)(b * TT + t0 + ty + i * 8) * N_EMBD + h * HD + d0 + tx];
    __syncthreads();
#pragma unroll
    for (int i = 0; i < 4; i++) {
        int d = ty + i * 8;
        vt[(size_t)(bh * HD + d0 + d) * TT + t0 + tx] = tile[tx][d];
    }
}

__global__ void rope_table_kernel() {
    int idx = blockIdx.x * blockDim.x + threadIdx.x;
    if (idx >= TT * 64) return;
    int t = idx >> 6;
    int i = idx & 63;
    double theta = pow(10000.0, -(double)i / 64.0);
    double ang = (double)t * theta;
    g_cos[idx] = (float)cos(ang);
    g_sin[idx] = (float)sin(ang);
}

// ---------------------------------------------------------------------------
// GEMM config (single-fp16 A now)
// ---------------------------------------------------------------------------
#define BM 128
#define BK 32
#define PADB 80
#define A_BYTES (128 * PADB)                     // 10240 (one A matrix)

// QKV: BN=192 -> 1024 CTAs -> 98.8% wave efficiency
#define BN6 192
#define B6_BYTES (192 * PADB)
#define STG6 (A_BYTES + B6_BYTES)                // 25600
#define QKV_SMEM (2 * STG6)                      // 51200

// Proj: BN=256
#define BN4 256
#define B4_BYTES (256 * PADB)
#define STG4 (A_BYTES + B4_BYTES)                // 30720
#define PROJ_SMEM (2 * STG4)                     // 61440

// ---------------------------------------------------------------------------
// QKV GEMM (BN=192, single-term) with fused RoPE/convert epilogue.
// ---------------------------------------------------------------------------
__global__ __launch_bounds__(256, 1) void gemm_qkv_kernel(
    const __half* __restrict__ A, const __half* __restrict__ B,
    __half* __restrict__ Q, __half* __restrict__ Kb, __half* __restrict__ Vh)
{
    const int K = N_EMBD;
    extern __shared__ char smc[];
    const uint32_t sbase = smem_u32(smc);
    const int tid = threadIdx.x;
    const int lane = tid & 31;
    const int wid = tid >> 5;
    const int wm = wid & 1;
    const int wn = wid >> 1;
    const int mBase = blockIdx.y * BM;
    const int nBase = blockIdx.x * BN6;
    const int nch = K / BK;

    const int ldRow = tid >> 2;
    const int ldCh  = tid & 3;

    float acc[4][6][4];
#pragma unroll
    for (int i = 0; i < 4; i++)
#pragma unroll
        for (int j = 0; j < 6; j++)
#pragma unroll
            for (int r = 0; r < 4; r++) acc[i][j][r] = 0.0f;

    auto issue_stage = [&](int c, int buf) {
        const uint32_t st = sbase + buf * STG6;
        const int kOff = c * BK;
#pragma unroll
        for (int i = 0; i < 2; i++) {
            const int row = i * 64 + ldRow;
            const uint32_t so = row * PADB + ldCh * 16;
            CP_ASYNC16(st + so,
                       A + (size_t)(mBase + row) * K + kOff + ldCh * 8);
        }
#pragma unroll
        for (int i = 0; i < 3; i++) {
            const int row = i * 64 + ldRow;
            const uint32_t so = row * PADB + ldCh * 16;
            CP_ASYNC16(st + A_BYTES + so,
                       B + (size_t)(nBase + row) * K + kOff + ldCh * 8);
        }
    };

    issue_stage(0, 0);
    CP_COMMIT();

    const int arow = (lane & 7) + ((lane >> 3) & 1) * 8;
    const int akc8 = (lane >> 4) * 8;
    const int brow = (lane & 7) + ((lane >> 4) & 1) * 8;
    const int bkc8 = ((lane >> 3) & 1) * 8;

    for (int c = 0; c < nch; c++) {
        const int buf = c & 1;
        if (c + 1 < nch) issue_stage(c + 1, (c + 1) & 1);
        CP_COMMIT();
        CP_WAIT1();
        __syncthreads();

        const uint32_t st = sbase + buf * STG6;
        const uint32_t aB = st;
        const uint32_t bB = st + A_BYTES;

#pragma unroll
        for (int s = 0; s < 2; s++) {
            const int kofs = s * 16;
            uint32_t af[4][4];
#pragma unroll
            for (int fm = 0; fm < 4; fm++) {
                const uint32_t off =
                    (uint32_t)((wm * 64 + fm * 16 + arow) * PADB +
                               (kofs + akc8) * 2);
                ldsm_x4(af[fm], aB + off);
            }
#pragma unroll
            for (int bi = 0; bi < 3; bi++) {
                uint32_t bf[4];
                const uint32_t off =
                    (uint32_t)((wn * 48 + bi * 16 + brow) * PADB +
                               (kofs + bkc8) * 2);
                ldsm_x4(bf, bB + off);
#pragma unroll
                for (int fm = 0; fm < 4; fm++) {
                    mma16816(acc[fm][2 * bi],     af[fm], bf);
                    mma16816(acc[fm][2 * bi + 1], af[fm], bf + 2);
                }
            }
        }
        __syncthreads();
    }

    // ---- fused epilogue ----
    const int r0 = lane >> 2;
    const int c0 = (lane & 3) * 2;
#pragma unroll
    for (int fm = 0; fm < 4; fm++) {
        const int row = mBase + wm * 64 + fm * 16 + r0;
        const int t0 = row & (TT - 1);
        const int t1 = (row + 8) & (TT - 1);
#pragma unroll
        for (int fn = 0; fn < 6; fn++) {
            const float v0 = acc[fm][fn][0], v1 = acc[fm][fn][1];
            const float v2 = acc[fm][fn][2], v3 = acc[fm][fn][3];
            const int col = nBase + wn * 48 + fn * 8 + c0;
            const int sec = col >> 11;
            const int cloc = col & (N_EMBD - 1);
            if (sec < 2) {
                const int i0 = (cloc & 127) >> 1;
                float cA = g_cos[t0 * 64 + i0], sA = g_sin[t0 * 64 + i0];
                float cB = g_cos[t1 * 64 + i0], sB = g_sin[t1 * 64 + i0];
                float r00 = v0 * cA - v1 * sA, r01 = v1 * cA + v0 * sA;
                float r10 = v2 * cB - v3 * sB, r11 = v3 * cB + v2 * sB;
                __half* dst = (sec == 0) ? Q : Kb;
                *(uint32_t*)(dst + (size_t)row * N_EMBD + cloc) =
                    pack_h(r00, r01);
                *(uint32_t*)(dst + (size_t)(row + 8) * N_EMBD + cloc) =
                    pack_h(r10, r11);
            } else {
                *(uint32_t*)(Vh + (size_t)row * N_EMBD + cloc) =
                    pack_h(v0, v1);
                *(uint32_t*)(Vh + (size_t)(row + 8) * N_EMBD + cloc) =
                    pack_h(v2, v3);
            }
        }
    }
}

// ---------------------------------------------------------------------------
// Proj GEMM (BN=256, single-term): fp32 out
// ---------------------------------------------------------------------------
__global__ __launch_bounds__(256, 1) void gemm_proj_kernel(
    const __half* __restrict__ A, const __half* __restrict__ B,
    float* __restrict__ C, int M, int N, int K)
{
    extern __shared__ char smc[];
    const uint32_t sbase = smem_u32(smc);
    const int tid = threadIdx.x;
    const int lane = tid & 31;
    const int wid = tid >> 5;
    const int wm = wid & 1;
    const int wn = wid >> 1;
    const int mBase = blockIdx.y * BM;
    const int nBase = blockIdx.x * BN4;
    const int nch = K / BK;

    const int ldRow = tid >> 2;
    const int ldCh  = tid & 3;

    float acc[4][8][4];
#pragma unroll
    for (int i = 0; i < 4; i++)
#pragma unroll
        for (int j = 0; j < 8; j++)
#pragma unroll
            for (int r = 0; r < 4; r++) acc[i][j][r] = 0.0f;

    auto issue_stage = [&](int c, int buf) {
        const uint32_t st = sbase + buf * STG4;
        const int kOff = c * BK;
#pragma unroll
        for (int i = 0; i < 2; i++) {
            const int row = i * 64 + ldRow;
            const uint32_t so = row * PADB + ldCh * 16;
            CP_ASYNC16(st + so,
                       A + (size_t)(mBase + row) * K + kOff + ldCh * 8);
        }
#pragma unroll
        for (int i = 0; i < 4; i++) {
            const int row = i * 64 + ldRow;
            const uint32_t so = row * PADB + ldCh * 16;
            CP_ASYNC16(st + A_BYTES + so,
                       B + (size_t)(nBase + row) * K + kOff + ldCh * 8);
        }
    };

    issue_stage(0, 0);
    CP_COMMIT();

    const int arow = (lane & 7) + ((lane >> 3) & 1) * 8;
    const int akc8 = (lane >> 4) * 8;
    const int brow = (lane & 7) + ((lane >> 4) & 1) * 8;
    const int bkc8 = ((lane >> 3) & 1) * 8;

    for (int c = 0; c < nch; c++) {
        const int buf = c & 1;
        if (c + 1 < nch) issue_stage(c + 1, (c + 1) & 1);
        CP_COMMIT();
        CP_WAIT1();
        __syncthreads();

        const uint32_t st = sbase + buf * STG4;
        const uint32_t aB = st;
        const uint32_t bB = st + A_BYTES;

#pragma unroll
        for (int s = 0; s < 2; s++) {
            const int kofs = s * 16;
            uint32_t af[4][4];
#pragma unroll
            for (int fm = 0; fm < 4; fm++) {
                const uint32_t off =
                    (uint32_t)((wm * 64 + fm * 16 + arow) * PADB +
                               (kofs + akc8) * 2);
                ldsm_x4(af[fm], aB + off);
            }
#pragma unroll
            for (int bi = 0; bi < 4; bi++) {
                uint32_t bf[4];
                const uint32_t off =
                    (uint32_t)((wn * 64 + bi * 16 + brow) * PADB +
                               (kofs + bkc8) * 2);
                ldsm_x4(bf, bB + off);
#pragma unroll
                for (int fm = 0; fm < 4; fm++) {
                    mma16816(acc[fm][2 * bi],     af[fm], bf);
                    mma16816(acc[fm][2 * bi + 1], af[fm], bf + 2);
                }
            }
        }
        __syncthreads();
    }

    const int r0 = lane >> 2;
    const int c0 = (lane & 3) * 2;
#pragma unroll
    for (int fm = 0; fm < 4; fm++) {
#pragma unroll
        for (int fn = 0; fn < 8; fn++) {
            const size_t row = (size_t)(mBase + wm * 64 + fm * 16 + r0);
            const int col = nBase + wn * 64 + fn * 8 + c0;
            *(float2*)(C + row * N + col) =
                make_float2(acc[fm][fn][0], acc[fm][fn][1]);
            *(float2*)(C + (row + 8) * N + col) =
                make_float2(acc[fm][fn][2], acc[fm][fn][3]);
        }
    }
}

// ---------------------------------------------------------------------------
// Flash attention: single fp16 Q, K, P, V. Epilogue writes single fp16 O.
// ---------------------------------------------------------------------------
#define FQ_BYTES   (128 * 272)
#define FK_BYTES   (64 * 272)
#define FV_BYTES   (128 * 144)
#define FSTAGE     (FK_BYTES + FV_BYTES)
#define FA_SMEM    (FQ_BYTES + 2 * FSTAGE)       // 106496

__global__ __launch_bounds__(256, 1) void flash_mma_kernel(
    const __half* __restrict__ q, const __half* __restrict__ kh,
    const __half* __restrict__ vt, __half* __restrict__ y)
{
    extern __shared__ char smc[];
    const uint32_t sbase = smem_u32(smc);
    const int tid = threadIdx.x;
    const int lane = tid & 31;
    const int wid = tid >> 5;
    const int b = blockIdx.z, h = blockIdx.y;
    const int bh = b * NH + h;
    const int q0 = blockIdx.x * 128;
    const size_t bT = (size_t)b * TT;
    const int hoff = h * HD;

    {
#pragma unroll
        for (int i = 0; i < 8; i++) {
            int cid = i * 256 + tid;
            int row = cid >> 4, ch = cid & 15;
            CP_ASYNC16(sbase + row * 272 + ch * 16,
                       q + (bT + q0 + row) * N_EMBD + hoff + ch * 8);
        }
        CP_COMMIT();
    }

    auto issue_stage = [&](int it, int buf) {
        const uint32_t st = sbase + FQ_BYTES + buf * FSTAGE;
        const int n0 = it * 64;
#pragma unroll
        for (int i = 0; i < 4; i++) {
            int cid = i * 256 + tid;
            int row = cid >> 4, ch = cid & 15;
            CP_ASYNC16(st + row * 272 + ch * 16,
                       kh + (bT + n0 + row) * N_EMBD + hoff + ch * 8);
        }
#pragma unroll
        for (int i = 0; i < 4; i++) {
            int cid = i * 256 + tid;
            int row = cid >> 3, ch = cid & 7;
            CP_ASYNC16(st + FK_BYTES + row * 144 + ch * 16,
                       vt + (size_t)(bh * HD + row) * TT + n0 + ch * 8);
        }
    };

    issue_stage(0, 0);
    CP_COMMIT();

    const int arow = (lane & 7) + ((lane >> 3) & 1) * 8;
    const int aoff = (lane >> 4) * 16;
    const int brow = (lane & 7) + ((lane >> 4) & 1) * 8;
    const int boff = ((lane >> 3) & 1) * 16;
    const int g = lane >> 2;
    const int tq = lane & 3;

    float O[16][4];
#pragma unroll
    for (int i = 0; i < 16; i++)
#pragma unroll
        for (int r = 0; r < 4; r++) O[i][r] = 0.0f;
    float ma = -INFINITY, mb = -INFINITY, la = 0.0f, lb = 0.0f;
    const float sc = 0.08838834764831845f;

    const int niter = TT / 64;
    for (int c = 0; c < niter; c++) {
        const int buf = c & 1;
        if (c + 1 < niter) issue_stage(c + 1, (c + 1) & 1);
        CP_COMMIT();
        CP_WAIT1();
        __syncthreads();

        const uint32_t kb = sbase + FQ_BYTES + buf * FSTAGE;

        float s[8][4];
#pragma unroll
        for (int j = 0; j < 8; j++)
#pragma unroll
            for (int r = 0; r < 4; r++) s[j][r] = 0.0f;

#pragma unroll
        for (int kk = 0; kk < 8; kk++) {
            uint32_t qf[4];
            const uint32_t qo = (wid * 16 + arow) * 272 + kk * 32 + aoff;
            ldsm_x4(qf, sbase + qo);
#pragma unroll
            for (int bp = 0; bp < 2; bp++) {
                uint32_t khf[2][4];
#pragma unroll
                for (int u = 0; u < 2; u++) {
                    const int bi = 2 * bp + u;
                    const uint32_t ko = (bi * 16 + brow) * 272 + kk * 32 + boff;
                    ldsm_x4(khf[u], kb + ko);
                }
#pragma unroll
                for (int u = 0; u < 2; u++) {
                    const int bi = 2 * bp + u;
                    mma16816(s[2 * bi],     qf, khf[u]);
                    mma16816(s[2 * bi + 1], qf, khf[u] + 2);
                }
            }
        }

        float mxa = -INFINITY, mxb = -INFINITY;
#pragma unroll
        for (int j = 0; j < 8; j++) {
            s[j][0] *= sc; s[j][1] *= sc; s[j][2] *= sc; s[j][3] *= sc;
            mxa = fmaxf(mxa, fmaxf(s[j][0], s[j][1]));
            mxb = fmaxf(mxb, fmaxf(s[j][2], s[j][3]));
        }
        mxa = fmaxf(mxa, __shfl_xor_sync(0xffffffffu, mxa, 1));
        mxa = fmaxf(mxa, __shfl_xor_sync(0xffffffffu, mxa, 2));
        mxb = fmaxf(mxb, __shfl_xor_sync(0xffffffffu, mxb, 1));
        mxb = fmaxf(mxb, __shfl_xor_sync(0xffffffffu, mxb, 2));
        float mna = fmaxf(ma, mxa), mnb = fmaxf(mb, mxb);
        float alpha = __expf(ma - mna), beta = __expf(mb - mnb);
        ma = mna; mb = mnb;
        float sua = 0.0f, sub = 0.0f;
#pragma unroll
        for (int j = 0; j < 8; j++) {
            s[j][0] = __expf(s[j][0] - mna);
            s[j][1] = __expf(s[j][1] - mna);
            s[j][2] = __expf(s[j][2] - mnb);
            s[j][3] = __expf(s[j][3] - mnb);
            sua += s[j][0] + s[j][1];
            sub += s[j][2] + s[j][3];
        }
        sua += __shfl_xor_sync(0xffffffffu, sua, 1);
        sua += __shfl_xor_sync(0xffffffffu, sua, 2);
        sub += __shfl_xor_sync(0xffffffffu, sub, 1);
        sub += __shfl_xor_sync(0xffffffffu, sub, 2);
        la = la * alpha + sua;
        lb = lb * beta + sub;
#pragma unroll
        for (int j2 = 0; j2 < 16; j2++) {
            O[j2][0] *= alpha; O[j2][1] *= alpha;
            O[j2][2] *= beta;  O[j2][3] *= beta;
        }

        uint32_t Ph[4][4];
#pragma unroll
        for (int kp = 0; kp < 4; kp++) {
            Ph[kp][0] = pack_h(s[2 * kp][0],     s[2 * kp][1]);
            Ph[kp][1] = pack_h(s[2 * kp][2],     s[2 * kp][3]);
            Ph[kp][2] = pack_h(s[2 * kp + 1][0], s[2 * kp + 1][1]);
            Ph[kp][3] = pack_h(s[2 * kp + 1][2], s[2 * kp + 1][3]);
        }

        const uint32_t vb = kb + FK_BYTES;
#pragma unroll
        for (int kp = 0; kp < 4; kp++) {
#pragma unroll
            for (int jp = 0; jp < 4; jp++) {
                uint32_t vhf[2][4];
#pragma unroll
                for (int u = 0; u < 2; u++) {
                    const int j4 = 2 * jp + u;
                    const uint32_t vo = (j4 * 16 + brow) * 144 + kp * 32 + boff;
                    ldsm_x4(vhf[u], vb + vo);
                }
#pragma unroll
                for (int u = 0; u < 2; u++) {
                    const int j4 = 2 * jp + u;
                    mma16816(O[2 * j4],     Ph[kp], vhf[u]);
                    mma16816(O[2 * j4 + 1], Ph[kp], vhf[u] + 2);
                }
            }
        }
        __syncthreads();
    }

    // ---- epilogue: normalize + single fp16 write into g_A (proj input) ----
    const float inva = 1.0f / la, invb = 1.0f / lb;
    const size_t rowa = bT + q0 + wid * 16 + g;
    const size_t rowb = rowa + 8;
#pragma unroll
    for (int j2 = 0; j2 < 16; j2++) {
        const int col = hoff + j2 * 8 + tq * 2;
        *(uint32_t*)(y + rowa * N_EMBD + col) =
            pack_h(O[j2][0] * inva, O[j2][1] * inva);
        *(uint32_t*)(y + rowb * N_EMBD + col) =
            pack_h(O[j2][2] * invb, O[j2][3] * invb);
    }
}

// ---------------------------------------------------------------------------
// Launch
// ---------------------------------------------------------------------------
extern "C" void kernel_launch(void* const* d_in, const int* in_sizes, int n_in,
                              void* d_out, int out_size)
{
    const float* x      = (const float*)d_in[0];
    const float* w_attn = (const float*)d_in[1];
    const float* w_proj = (const float*)d_in[2];
    float* out = (float*)d_out;

    __half *A, *Wa, *Wp, *Q, *Kb, *Vh, *Vt;
    cudaGetSymbolAddress((void**)&A, g_A);
    cudaGetSymbolAddress((void**)&Wa, g_Wa);
    cudaGetSymbolAddress((void**)&Wp, g_Wp);
    cudaGetSymbolAddress((void**)&Q, g_Q);
    cudaGetSymbolAddress((void**)&Kb, g_K);
    cudaGetSymbolAddress((void**)&Vh, g_Vh);
    cudaGetSymbolAddress((void**)&Vt, g_Vt);

    cudaFuncSetAttribute(gemm_qkv_kernel,
                         cudaFuncAttributeMaxDynamicSharedMemorySize, QKV_SMEM);
    cudaFuncSetAttribute(gemm_proj_kernel,
                         cudaFuncAttributeMaxDynamicSharedMemorySize, PROJ_SMEM);
    cudaFuncSetAttribute(flash_mma_kernel,
                         cudaFuncAttributeMaxDynamicSharedMemorySize, FA_SMEM);

    const int n4 = MROWS * N_EMBD / 4;

    rope_table_kernel<<<(TT * 64 + 255) / 256, 256>>>();

    conv_single_kernel<<<(n4 + 255) / 256, 256>>>(x, A, n4);
    conv_tr_kernel<<<dim3(QKV_N / 32, N_EMBD / 32), dim3(32, 8)>>>(
        w_attn, Wa, N_EMBD, QKV_N);
    conv_tr_kernel<<<dim3(N_EMBD / 32, N_EMBD / 32), dim3(32, 8)>>>(
        w_proj, Wp, N_EMBD, N_EMBD);

    // QKV projection (single-term, fused RoPE epilogue)
    gemm_qkv_kernel<<<dim3(QKV_N / BN6, MROWS / BM), 256, QKV_SMEM>>>(
        A, Wa, Q, Kb, Vh);

    conv_vth_kernel<<<dim3(TT / 32, HD / 32, BB * NH), dim3(32, 8)>>>(Vh, Vt);

    // Flash attention (single fp16) -> y (single fp16) into g_A
    flash_mma_kernel<<<dim3(TT / 128, NH, BB), 256, FA_SMEM>>>(
        Q, Kb, Vt, A);

    // Output projection (single-term, fp32 out)
    gemm_proj_kernel<<<dim3(N_EMBD / BN4, MROWS / BM), 256, PROJ_SMEM>>>(
        A, Wp, out, MROWS, N_EMBD, N_EMBD);
}